// round 2
// baseline (speedup 1.0000x reference)
#include <cuda_runtime.h>
#include <cstdint>

#define PADC 8
#define CV 256

// ---------------- static device buffers (no allocation allowed) ----------------
// corr per level: 2*289*HW  -> offsets {0, 9469952, 11837440, 12429312}, total 12577280
// map  per level: 2*256*HW  -> offsets {0, 8388608, 10485760, 11010048}, total 11141120
__device__ float g_corr[12577280];
__device__ float g_map [11141120];
__device__ float g_wmT [4 * 7209 * 256];   // packed [K x 256] per level
__device__ float g_woT [4 * 2304 * 256];

// ---------------- f32x2 helpers (Blackwell packed fp32 FMA) ----------------
__device__ __forceinline__ unsigned long long pk2(float a, float b){
    unsigned long long r; asm("mov.b64 %0, {%1,%2};" : "=l"(r) : "f"(a), "f"(b)); return r;
}
__device__ __forceinline__ void fma2(unsigned long long &d, unsigned long long a, unsigned long long b){
    asm("fma.rn.f32x2 %0, %1, %2, %0;" : "+l"(d) : "l"(a), "l"(b));
}
__device__ __forceinline__ float2 upk(unsigned long long v){
    float2 f; asm("mov.b64 {%0,%1}, %2;" : "=f"(f.x), "=f"(f.y) : "l"(v)); return f;
}

// ---------------- weight transpose: in[co*cols + k] -> out[k*256 + co] ----------------
__global__ void k_transpose(const float* __restrict__ in, float* __restrict__ out,
                            int rows, int cols){
    __shared__ float t[32][33];
    int c0 = blockIdx.x * 32, r0 = blockIdx.y * 32;
    int cx = c0 + threadIdx.x;
    #pragma unroll
    for (int dy = 0; dy < 32; dy += 8){
        int rr = r0 + threadIdx.y + dy;
        t[threadIdx.y + dy][threadIdx.x] = (rr < rows && cx < cols) ? in[rr * cols + cx] : 0.f;
    }
    __syncthreads();
    int rr2 = r0 + threadIdx.x;
    #pragma unroll
    for (int dy = 0; dy < 32; dy += 8){
        int cc = c0 + threadIdx.y + dy;
        if (cc < cols && rr2 < rows) out[cc * rows + rr2] = t[threadIdx.x][threadIdx.y + dy];
    }
}

// ---------------- correlation ----------------
// thread: (group g of 4 pixels, dy). acc[dj][p] over c. block: (w-tile, h, b)
__global__ void k_corr(const float* __restrict__ x, const float* __restrict__ ref,
                       float* __restrict__ corr, int H, int W, int groups){
    int g  = threadIdx.x % groups;
    int dy = threadIdx.x / groups;
    if (dy >= 17) return;
    int w0 = blockIdx.x * groups * 4;
    int h  = blockIdx.y;
    int b  = blockIdx.z;
    int wbase = w0 + g * 4;

    float acc[17][4];
    #pragma unroll
    for (int j = 0; j < 17; j++){
        acc[j][0]=0.f; acc[j][1]=0.f; acc[j][2]=0.f; acc[j][3]=0.f;
    }

    int r = h + dy - PADC;
    int HW = H * W;
    if (r >= 0 && r < H){
        const float* xb = x   + ((b * CV) * H + h) * W;
        const float* rb = ref + ((b * CV) * H + r) * W;
        int q0 = wbase - PADC;
        bool interior = (q0 >= 0) && (q0 + 20 <= W);
        for (int c = 0; c < CV; c++){
            const float4 xv = *reinterpret_cast<const float4*>(xb + c * HW + wbase);
            const float* rr = rb + c * HW;
            float rv[20];
            if (interior){
                #pragma unroll
                for (int t = 0; t < 5; t++){
                    float4 v = *reinterpret_cast<const float4*>(rr + q0 + t * 4);
                    rv[t*4+0]=v.x; rv[t*4+1]=v.y; rv[t*4+2]=v.z; rv[t*4+3]=v.w;
                }
            } else {
                #pragma unroll
                for (int t = 0; t < 20; t++){
                    int q = q0 + t;
                    rv[t] = (q >= 0 && q < W) ? rr[q] : 0.f;
                }
            }
            #pragma unroll
            for (int j = 0; j < 17; j++){
                acc[j][0] += xv.x * rv[j];
                acc[j][1] += xv.y * rv[j+1];
                acc[j][2] += xv.z * rv[j+2];
                acc[j][3] += xv.w * rv[j+3];
            }
        }
    }
    #pragma unroll
    for (int j = 0; j < 17; j++){
        int d = dy * 17 + j;
        float4 o; o.x = acc[j][0]; o.y = acc[j][1]; o.z = acc[j][2]; o.w = acc[j][3];
        *reinterpret_cast<float4*>(corr + ((b * 289 + d) * H + h) * W + wbase) = o;
    }
}

// ---------------- init output region with per-channel bias ----------------
__global__ void k_init_bias(float* __restrict__ out, const float* __restrict__ bias,
                            int HW, int total){
    int i = blockIdx.x * blockDim.x + threadIdx.x;
    if (i < total) out[i] = bias[(i / HW) & 255];
}

// ---------------- nearest x2 upsample add: dst[b,c,h,w] += src[b,c,h/2,w/2] ----------------
__global__ void k_up_add(float* __restrict__ dst, const float* __restrict__ src,
                         int H, int W, int total){
    int i = blockIdx.x * blockDim.x + threadIdx.x;
    if (i >= total) return;
    int w = i % W; int t = i / W; int h = t % H; int bc = t / H;
    dst[i] += src[(bc * (H >> 1) + (h >> 1)) * (W >> 1) + (w >> 1)];
}

// ---------------- implicit-im2col SGEMM conv3x3 (pad 1), f32x2 inner ----------------
// out[b,co,h,w] = bias[co] + sum_{ci,tap} A[(ci*9+tap)*256+co] * src(ci)[b, h+dy, w+dx]
// source = concat(S0[C0], S1[C1], S2[C2]) along channels. K split over ci via blockIdx.z.
__global__ __launch_bounds__(256, 2)
void k_conv_gemm(const float* __restrict__ A,
                 const float* __restrict__ S0, int C0,
                 const float* __restrict__ S1, int C1,
                 const float* __restrict__ S2, int C2,
                 int H, int W, int Cin,
                 float* __restrict__ out, const float* __restrict__ bias,
                 int useAtomic)
{
    __shared__ __align__(16) float As[2][9][128];
    __shared__ __align__(16) float Bs[2][9][128];
    __shared__ int sb[128], sh[128], sw[128];

    const int HW  = H * W;
    const int tid = threadIdx.x;
    const int n0  = blockIdx.x * 128;
    const int m0  = blockIdx.y * 128;

    const int gz    = gridDim.z;
    const int per   = (Cin + gz - 1) / gz;
    const int ciBeg = blockIdx.z * per;
    if (ciBeg >= Cin) return;
    const int ciEnd = (ciBeg + per < Cin) ? (ciBeg + per) : Cin;

    if (tid < 128){
        int p = n0 + tid;
        int b = p / HW; int rmd = p - b * HW;
        sb[tid] = b; sh[tid] = rmd / W; sw[tid] = rmd % W;
    }
    __syncthreads();

    float rA[5], rB[5];
    auto loadTile = [&](int ci){
        const float* sp; int cl, Cs;
        if (ci < C0)            { sp = S0; cl = ci;            Cs = C0; }
        else if (ci < C0 + C1)  { sp = S1; cl = ci - C0;       Cs = C1; }
        else                    { sp = S2; cl = ci - C0 - C1;  Cs = C2; }
        const float* Arow = A + ci * 9 * 256 + m0;
        #pragma unroll
        for (int i = 0; i < 5; i++){
            int e = tid + i * 256;
            if (e < 1152){
                int kl = e >> 7; int col = e & 127;
                rA[i] = Arow[kl * 256 + col];
                int ky = kl / 3;
                int hh = sh[col] + ky - 1;
                int ww = sw[col] + (kl - ky * 3) - 1;
                float v = 0.f;
                if ((unsigned)hh < (unsigned)H && (unsigned)ww < (unsigned)W)
                    v = sp[(sb[col] * Cs + cl) * HW + hh * W + ww];
                rB[i] = v;
            }
        }
    };
    auto storeTile = [&](int bufw){
        #pragma unroll
        for (int i = 0; i < 5; i++){
            int e = tid + i * 256;
            if (e < 1152){
                int kl = e >> 7; int col = e & 127;
                As[bufw][kl][col] = rA[i];
                Bs[bufw][kl][col] = rB[i];
            }
        }
    };

    unsigned long long acc[8][4];
    #pragma unroll
    for (int i = 0; i < 8; i++)
        #pragma unroll
        for (int j = 0; j < 4; j++) acc[i][j] = 0ull;

    const int tx = tid & 15, ty = tid >> 4;

    loadTile(ciBeg);
    storeTile(0);
    __syncthreads();

    int buf = 0;
    for (int ci = ciBeg; ci < ciEnd; ++ci){
        bool hasNext = (ci + 1 < ciEnd);
        if (hasNext) loadTile(ci + 1);
        #pragma unroll
        for (int k = 0; k < 9; k++){
            float4 a0 = *reinterpret_cast<const float4*>(&As[buf][k][ty * 8]);
            float4 a1 = *reinterpret_cast<const float4*>(&As[buf][k][ty * 8 + 4]);
            float4 b0 = *reinterpret_cast<const float4*>(&Bs[buf][k][tx * 8]);
            float4 b1 = *reinterpret_cast<const float4*>(&Bs[buf][k][tx * 8 + 4]);
            unsigned long long bp0 = pk2(b0.x, b0.y);
            unsigned long long bp1 = pk2(b0.z, b0.w);
            unsigned long long bp2 = pk2(b1.x, b1.y);
            unsigned long long bp3 = pk2(b1.z, b1.w);
            float av[8] = {a0.x, a0.y, a0.z, a0.w, a1.x, a1.y, a1.z, a1.w};
            #pragma unroll
            for (int i = 0; i < 8; i++){
                unsigned long long ap = pk2(av[i], av[i]);
                fma2(acc[i][0], ap, bp0);
                fma2(acc[i][1], ap, bp1);
                fma2(acc[i][2], ap, bp2);
                fma2(acc[i][3], ap, bp3);
            }
        }
        if (hasNext){ storeTile(buf ^ 1); __syncthreads(); buf ^= 1; }
    }

    #pragma unroll
    for (int i = 0; i < 8; i++){
        int co = m0 + ty * 8 + i;
        float bv = useAtomic ? 0.f : bias[co];
        #pragma unroll
        for (int j = 0; j < 4; j++){
            float2 v = upk(acc[i][j]);
            int lp0 = tx * 8 + j * 2;          // LOCAL pixel index within the 128-tile
            int lp1 = lp0 + 1;
            int a0i = (sb[lp0] * 256 + co) * HW + sh[lp0] * W + sw[lp0];
            int a1i = (sb[lp1] * 256 + co) * HW + sh[lp1] * W + sw[lp1];
            if (useAtomic){
                atomicAdd(&out[a0i], v.x);
                atomicAdd(&out[a1i], v.y);
            } else {
                out[a0i] = v.x + bv;
                out[a1i] = v.y + bv;
            }
        }
    }
}

// ---------------- host orchestration ----------------
extern "C" void kernel_launch(void* const* d_in, const int* in_sizes, int n_in,
                              void* d_out, int out_size)
{
    const float *x[4]={0,0,0,0}, *rx[4]={0,0,0,0};
    const float *wm[4]={0,0,0,0}, *bm[4]={0,0,0,0}, *wo[4]={0,0,0,0}, *bo[4]={0,0,0,0};
    int wmi = 0, woi = 0, bi = 0;
    for (int i = 0; i < n_in; i++){
        int s = in_sizes[i];
        int lvl = -1;
        if      (s == 2*256*128*128) lvl = 0;
        else if (s == 2*256*64*64)   lvl = 1;
        else if (s == 2*256*32*32)   lvl = 2;
        else if (s == 2*256*16*16)   lvl = 3;
        if (lvl >= 0){
            if (!x[lvl]) x[lvl] = (const float*)d_in[i];
            else         rx[lvl] = (const float*)d_in[i];
        }
        else if (s == 1845504) wm[wmi++] = (const float*)d_in[i];   // 256*801*9
        else if (s ==  589824) wo[woi++] = (const float*)d_in[i];   // 256*256*9
        else if (s ==     256){
            if ((bi & 1) == 0) bm[bi >> 1] = (const float*)d_in[i];
            else               bo[bi >> 1] = (const float*)d_in[i];
            bi++;
        }
    }

    float *corrB, *mapB, *wmT, *woT;
    cudaGetSymbolAddress((void**)&corrB, g_corr);
    cudaGetSymbolAddress((void**)&mapB,  g_map);
    cudaGetSymbolAddress((void**)&wmT,   g_wmT);
    cudaGetSymbolAddress((void**)&woT,   g_woT);

    const int    Hl[4]      = {128, 64, 32, 16};
    const int    HWl[4]     = {16384, 4096, 1024, 256};
    const long   corrOff[4] = {0, 9469952, 11837440, 12429312};
    const long   mapOff[4]  = {0, 8388608, 10485760, 11010048};
    float* outp = (float*)d_out;

    // 1. pack weights: [256 x K] -> [K x 256]
    {
        dim3 tb(32, 8);
        for (int l = 0; l < 4; l++){
            dim3 g1((7209 + 31) / 32, 8);
            k_transpose<<<g1, tb>>>(wm[l], wmT + (long)l * 7209 * 256, 256, 7209);
            dim3 g2((2304 + 31) / 32, 8);
            k_transpose<<<g2, tb>>>(wo[l], woT + (long)l * 2304 * 256, 256, 2304);
        }
    }

    // 2. correlation volumes
    for (int l = 0; l < 4; l++){
        int W = Hl[l];
        int groups = (W >= 32) ? 8 : 4;
        dim3 g(W / (groups * 4), Hl[l], 2);
        k_corr<<<g, groups * 17>>>(x[l], rx[l], corrB + corrOff[l], Hl[l], W, groups);
    }

    // 3. map convs (801 -> 256), split-K for small levels
    const int ksm[4] = {1, 2, 8, 16};
    for (int l = 0; l < 4; l++){
        float* mout = mapB + mapOff[l];
        int total = 2 * 256 * HWl[l];
        if (ksm[l] > 1)
            k_init_bias<<<(total + 255) / 256, 256>>>(mout, bm[l], HWl[l], total);
        dim3 g(2 * HWl[l] / 128, 2, ksm[l]);
        k_conv_gemm<<<g, 256>>>(wmT + (long)l * 7209 * 256,
                                x[l], 256, rx[l], 256, corrB + corrOff[l], 289,
                                Hl[l], Hl[l], 801,
                                mout, bm[l], ksm[l] > 1 ? 1 : 0);
    }

    // 4. top-down upsample-add (sequential: 3->2->1->0)
    for (int l = 3; l >= 1; l--){
        int total = 2 * 256 * HWl[l - 1];
        k_up_add<<<(total + 255) / 256, 256>>>(mapB + mapOff[l - 1], mapB + mapOff[l],
                                               Hl[l - 1], Hl[l - 1], total);
    }

    // 5. out convs (256 -> 256) -> d_out, split-K for small levels
    const int kso[4] = {1, 2, 8, 16};
    for (int l = 0; l < 4; l++){
        float* oo = outp + mapOff[l];
        int total = 2 * 256 * HWl[l];
        if (kso[l] > 1)
            k_init_bias<<<(total + 255) / 256, 256>>>(oo, bo[l], HWl[l], total);
        dim3 g(2 * HWl[l] / 128, 2, kso[l]);
        k_conv_gemm<<<g, 256>>>(woT + (long)l * 2304 * 256,
                                mapB + mapOff[l], 256, (const float*)0, 0, (const float*)0, 0,
                                Hl[l], Hl[l], 256,
                                oo, bo[l], kso[l] > 1 ? 1 : 0);
    }
}

// round 4
// speedup vs baseline: 1.4229x; 1.4229x over previous
#include <cuda_runtime.h>
#include <cuda_bf16.h>
#include <cstdint>
#include <cstddef>

#define PADC 8

// ---------------- static device buffers ----------------
__device__ float g_corr[12577280];            // corr volumes fp32
__device__ float g_map [11141120];            // map conv outputs fp32 NCHW
__device__ __nv_bfloat16 g_wm_h[7667712];     // map weights [lvl][tap][256][832]
__device__ __nv_bfloat16 g_wm_l[7667712];
__device__ __nv_bfloat16 g_wo_h[2359296];     // out weights [lvl][tap][256][256]
__device__ __nv_bfloat16 g_wo_l[2359296];
__device__ __nv_bfloat16 g_am_h[37832704];    // map acts padded NHWC [b][H+2][W+2][832]
__device__ __nv_bfloat16 g_am_l[37832704];
__device__ __nv_bfloat16 g_ao_h[11640832];    // out acts padded NHWC [b][H+2][W+2][256]
__device__ __nv_bfloat16 g_ao_l[11640832];

// ---------------- baseline-PTX helpers (compute_103-safe) ----------------
__device__ __forceinline__ uint32_t smem_u32(const void* p){
    uint32_t a;
    asm("{ .reg .u64 t; cvta.to.shared.u64 t, %1; cvt.u32.u64 %0, t; }" : "=r"(a) : "l"(p));
    return a;
}
__device__ __forceinline__ void cp16(uint32_t dst, const void* src){
    asm volatile("cp.async.cg.shared.global [%0], [%1], 16;" :: "r"(dst), "l"(src));
}
__device__ __forceinline__ void cp_commit(){ asm volatile("cp.async.commit_group;"); }
__device__ __forceinline__ void ldmx4(uint32_t* r, uint32_t addr){
    asm volatile("ldmatrix.sync.aligned.m8n8.x4.shared.b16 {%0,%1,%2,%3}, [%4];"
                 : "=r"(r[0]), "=r"(r[1]), "=r"(r[2]), "=r"(r[3]) : "r"(addr));
}
__device__ __forceinline__ void mma16816(float* c, const uint32_t* a, uint32_t b0, uint32_t b1){
    asm volatile(
        "mma.sync.aligned.m16n8k16.row.col.f32.bf16.bf16.f32 "
        "{%0,%1,%2,%3}, {%4,%5,%6,%7}, {%8,%9}, {%0,%1,%2,%3};"
        : "+f"(c[0]), "+f"(c[1]), "+f"(c[2]), "+f"(c[3])
        : "r"(a[0]), "r"(a[1]), "r"(a[2]), "r"(a[3]), "r"(b0), "r"(b1));
}

// ---------------- correlation (unchanged, validated) ----------------
__global__ void k_corr(const float* __restrict__ x, const float* __restrict__ ref,
                       float* __restrict__ corr, int H, int W, int groups){
    int g  = threadIdx.x % groups;
    int dy = threadIdx.x / groups;
    if (dy >= 17) return;
    int w0 = blockIdx.x * groups * 4;
    int h  = blockIdx.y;
    int b  = blockIdx.z;
    int wbase = w0 + g * 4;

    float acc[17][4];
    #pragma unroll
    for (int j = 0; j < 17; j++){ acc[j][0]=0.f; acc[j][1]=0.f; acc[j][2]=0.f; acc[j][3]=0.f; }

    int r = h + dy - PADC;
    int HW = H * W;
    if (r >= 0 && r < H){
        const float* xb = x   + ((b * 256) * H + h) * W;
        const float* rb = ref + ((b * 256) * H + r) * W;
        int q0 = wbase - PADC;
        bool interior = (q0 >= 0) && (q0 + 20 <= W);
        for (int c = 0; c < 256; c++){
            const float4 xv = *reinterpret_cast<const float4*>(xb + c * HW + wbase);
            const float* rr = rb + c * HW;
            float rv[20];
            if (interior){
                #pragma unroll
                for (int t = 0; t < 5; t++){
                    float4 v = *reinterpret_cast<const float4*>(rr + q0 + t * 4);
                    rv[t*4+0]=v.x; rv[t*4+1]=v.y; rv[t*4+2]=v.z; rv[t*4+3]=v.w;
                }
            } else {
                #pragma unroll
                for (int t = 0; t < 20; t++){
                    int q = q0 + t;
                    rv[t] = (q >= 0 && q < W) ? rr[q] : 0.f;
                }
            }
            #pragma unroll
            for (int j = 0; j < 17; j++){
                acc[j][0] += xv.x * rv[j];
                acc[j][1] += xv.y * rv[j+1];
                acc[j][2] += xv.z * rv[j+2];
                acc[j][3] += xv.w * rv[j+3];
            }
        }
    }
    #pragma unroll
    for (int j = 0; j < 17; j++){
        int d = dy * 17 + j;
        float4 o; o.x=acc[j][0]; o.y=acc[j][1]; o.z=acc[j][2]; o.w=acc[j][3];
        *reinterpret_cast<float4*>(corr + ((b * 289 + d) * H + h) * W + wbase) = o;
    }
}

// ---------------- misc small kernels ----------------
__global__ void k_init_bias(float* __restrict__ out, const float* __restrict__ bias,
                            int HW, int total){
    int i = blockIdx.x * blockDim.x + threadIdx.x;
    if (i < total) out[i] = bias[(i / HW) & 255];
}
__global__ void k_up_add(float* __restrict__ dst, const float* __restrict__ src,
                         int H, int W, int total){
    int i = blockIdx.x * blockDim.x + threadIdx.x;
    if (i >= total) return;
    int w = i % W; int t = i / W; int h = t % H; int bc = t / H;
    dst[i] += src[(bc * (H >> 1) + (h >> 1)) * (W >> 1) + (w >> 1)];
}

// ---------------- weight pack: w[co][ci][3][3] -> Wt[tap][co][Cpad] hi/lo bf16 ----------------
__global__ void k_pack_w(const float* __restrict__ w, __nv_bfloat16* __restrict__ oh,
                         __nv_bfloat16* __restrict__ ol, int Cin, int Cpad){
    int i = blockIdx.x * 256 + threadIdx.x;
    if (i >= 256 * Cpad) return;
    int co = i / Cpad, ci = i % Cpad;
    #pragma unroll
    for (int t = 0; t < 9; t++){
        float v = (ci < Cin) ? w[(size_t)(co * Cin + ci) * 9 + t] : 0.f;
        __nv_bfloat16 h = __float2bfloat16(v);
        float l = v - __bfloat162float(h);
        size_t o = ((size_t)t * 256 + co) * Cpad + ci;
        oh[o] = h;
        ol[o] = __float2bfloat16(l);
    }
}

// ---------------- activation pack: NCHW fp32 (up to 3 srcs) -> padded NHWC bf16 hi/lo ----------------
__global__ void k_pack_acts(const float* __restrict__ S0, int C0,
                            const float* __restrict__ S1, int C1,
                            const float* __restrict__ S2, int C2,
                            __nv_bfloat16* __restrict__ Ph, __nv_bfloat16* __restrict__ Pl,
                            int H, int W, int Cpad){
    __shared__ float t[32][33];
    int Hp = H + 2, Wp = W + 2, HW = H * W, Np = 2 * Hp * Wp;
    int p0 = blockIdx.x * 32, c0 = blockIdx.y * 32;
    int px = p0 + threadIdx.x;
    int b = 0, pix = 0; bool inter = false;
    if (px < Np){
        b = px / (Hp * Wp); int r = px % (Hp * Wp); int hp = r / Wp, wp = r % Wp;
        if (hp >= 1 && hp <= H && wp >= 1 && wp <= W){ inter = true; pix = (hp - 1) * W + (wp - 1); }
    }
    #pragma unroll
    for (int dyy = 0; dyy < 32; dyy += 8){
        int ci = c0 + (int)threadIdx.y + dyy;
        float v = 0.f;
        if (inter){
            if (ci < C0)                 v = S0[(size_t)(b * C0 + ci) * HW + pix];
            else if (ci < C0 + C1)       v = S1[(size_t)(b * C1 + ci - C0) * HW + pix];
            else if (ci < C0 + C1 + C2)  v = S2[(size_t)(b * C2 + (ci - C0 - C1)) * HW + pix];
        }
        t[threadIdx.y + dyy][threadIdx.x] = v;
    }
    __syncthreads();
    int ft = threadIdx.y * 32 + threadIdx.x;
    int pl = ft >> 3, sub = ft & 7;
    int px2 = p0 + pl;
    if (px2 < Np){
        size_t base = (size_t)px2 * Cpad + c0 + sub * 4;
        float v0 = t[sub*4+0][pl], v1 = t[sub*4+1][pl], v2 = t[sub*4+2][pl], v3 = t[sub*4+3][pl];
        __nv_bfloat16 h0 = __float2bfloat16(v0), h1 = __float2bfloat16(v1);
        __nv_bfloat16 h2 = __float2bfloat16(v2), h3 = __float2bfloat16(v3);
        uint32_t uh0 = (uint32_t)__bfloat16_as_ushort(h0) | ((uint32_t)__bfloat16_as_ushort(h1) << 16);
        uint32_t uh1 = (uint32_t)__bfloat16_as_ushort(h2) | ((uint32_t)__bfloat16_as_ushort(h3) << 16);
        uint2 wh; wh.x = uh0; wh.y = uh1;
        *reinterpret_cast<uint2*>(Ph + base) = wh;
        __nv_bfloat16 l0 = __float2bfloat16(v0 - __bfloat162float(h0));
        __nv_bfloat16 l1 = __float2bfloat16(v1 - __bfloat162float(h1));
        __nv_bfloat16 l2 = __float2bfloat16(v2 - __bfloat162float(h2));
        __nv_bfloat16 l3 = __float2bfloat16(v3 - __bfloat162float(h3));
        uint32_t ul0 = (uint32_t)__bfloat16_as_ushort(l0) | ((uint32_t)__bfloat16_as_ushort(l1) << 16);
        uint32_t ul1 = (uint32_t)__bfloat16_as_ushort(l2) | ((uint32_t)__bfloat16_as_ushort(l3) << 16);
        uint2 wl; wl.x = ul0; wl.y = ul1;
        *reinterpret_cast<uint2*>(Pl + base) = wl;
    }
}

// ---------------- mma.sync bf16 implicit conv GEMM (baseline PTX, tensor pipe) ----------------
// D[co 128, pix 128] per CTA; 3 passes {AhBh, AhBl, AlBh} x taps x ci-chunks(32).
// smem rows padded to 40 bf16 (80B) -> conflict-free ldmatrix.
__global__ __launch_bounds__(256, 2)
void k_gemm(const __nv_bfloat16* __restrict__ Ah, const __nv_bfloat16* __restrict__ Al,
            const __nv_bfloat16* __restrict__ Bh, const __nv_bfloat16* __restrict__ Bl,
            int H, int W, int Cpad, int tapsPerZ,
            float* __restrict__ out, const float* __restrict__ bias, int useAtomic)
{
    __shared__ __align__(16) __nv_bfloat16 Asm[2][128][40];
    __shared__ __align__(16) __nv_bfloat16 Bsm[2][128][40];
    __shared__ int offP[128];

    const int tid = threadIdx.x, wid = tid >> 5, lane = tid & 31;
    const int HW = H * W, Hp = H + 2, Wp = W + 2;
    const int n0 = blockIdx.x * 128;
    const int m0 = blockIdx.y * 128;
    const int tapBeg = blockIdx.z * tapsPerZ;
    const int CH = Cpad >> 5;                 // 32-ci chunks
    const int nIter = 3 * tapsPerZ * CH;

    if (tid < 128){
        int p = n0 + tid; int b = p / HW; int r = p - b * HW; int h = r / W; int w = r % W;
        offP[tid] = ((b * Hp + h) * Wp + w) * Cpad;
    }
    __syncthreads();

    const uint32_t AsmB[2] = {smem_u32(&Asm[0][0][0]), smem_u32(&Asm[1][0][0])};
    const uint32_t BsmB[2] = {smem_u32(&Bsm[0][0][0]), smem_u32(&Bsm[1][0][0])};

    const int segc = tid & 3;        // 16B segment within 64B row-chunk
    const int rowc = tid >> 2;       // 0..63

    auto stage = [&](int it, int buf){
        int pass = it / (tapsPerZ * CH);
        int rem  = it % (tapsPerZ * CH);
        int tap  = tapBeg + rem / CH;
        int ch   = rem % CH;
        const __nv_bfloat16* As = (pass == 2) ? Al : Ah;
        const __nv_bfloat16* Bs = (pass == 1) ? Bl : Bh;
        const __nv_bfloat16* A0 = As + (size_t)(tap * 256 + m0) * Cpad + ch * 32 + segc * 8;
        const __nv_bfloat16* B0 = Bs + (size_t)((tap / 3) * Wp + (tap % 3)) * Cpad + ch * 32 + segc * 8;
        #pragma unroll
        for (int j = 0; j < 2; j++){
            int row = rowc + j * 64;
            cp16(AsmB[buf] + row * 80 + segc * 16, A0 + (size_t)row * Cpad);
            cp16(BsmB[buf] + row * 80 + segc * 16, B0 + offP[row]);
        }
        cp_commit();
    };

    float acc[2][8][4];
    #pragma unroll
    for (int i = 0; i < 2; i++)
        #pragma unroll
        for (int j = 0; j < 8; j++)
            #pragma unroll
            for (int k = 0; k < 4; k++) acc[i][j][k] = 0.f;

    const int wm = wid & 3;          // 4 m-warps * 32 rows
    const int wn = wid >> 2;         // 2 n-warps * 64 cols
    // ldmatrix lane addressing
    const int lr = lane & 7;
    const int lm = (lane >> 3) & 1;
    const int lk = lane >> 4;
    const uint32_t laneOff = (uint32_t)((lm * 8 + lr) * 80 + lk * 16);

    stage(0, 0);
    for (int it = 0; it < nIter; ++it){
        int buf = it & 1;
        if (it + 1 < nIter){
            stage(it + 1, buf ^ 1);
            asm volatile("cp.async.wait_group 1;" ::: "memory");
        } else {
            asm volatile("cp.async.wait_group 0;" ::: "memory");
        }
        __syncthreads();

        #pragma unroll
        for (int ks = 0; ks < 2; ks++){
            uint32_t a[2][4];
            #pragma unroll
            for (int ma = 0; ma < 2; ma++)
                ldmx4(a[ma], AsmB[buf] + (uint32_t)((wm * 32 + ma * 16) * 80 + ks * 32) + laneOff);
            uint32_t bb[4][4];
            #pragma unroll
            for (int g = 0; g < 4; g++)
                ldmx4(bb[g], BsmB[buf] + (uint32_t)((wn * 64 + g * 16) * 80 + ks * 32) + laneOff);
            #pragma unroll
            for (int ma = 0; ma < 2; ma++)
                #pragma unroll
                for (int na = 0; na < 8; na++)
                    mma16816(acc[ma][na], a[ma], bb[na >> 1][na & 1], bb[na >> 1][2 + (na & 1)]);
        }
        __syncthreads();
    }

    // epilogue
    const int b = n0 / HW;
    const int pbase = n0 - b * HW;
    #pragma unroll
    for (int ma = 0; ma < 2; ma++){
        int co0 = m0 + wm * 32 + ma * 16 + (lane >> 2);
        int co1 = co0 + 8;
        float bv0 = useAtomic ? 0.f : bias[co0];
        float bv1 = useAtomic ? 0.f : bias[co1];
        size_t base0 = ((size_t)(b * 256 + co0)) * HW + pbase;
        size_t base1 = ((size_t)(b * 256 + co1)) * HW + pbase;
        #pragma unroll
        for (int na = 0; na < 8; na++){
            int pl = wn * 64 + na * 8 + (lane & 3) * 2;
            if (useAtomic){
                atomicAdd(&out[base0 + pl],     acc[ma][na][0]);
                atomicAdd(&out[base0 + pl + 1], acc[ma][na][1]);
                atomicAdd(&out[base1 + pl],     acc[ma][na][2]);
                atomicAdd(&out[base1 + pl + 1], acc[ma][na][3]);
            } else {
                float2 v0; v0.x = acc[ma][na][0] + bv0; v0.y = acc[ma][na][1] + bv0;
                float2 v1; v1.x = acc[ma][na][2] + bv1; v1.y = acc[ma][na][3] + bv1;
                *reinterpret_cast<float2*>(&out[base0 + pl]) = v0;
                *reinterpret_cast<float2*>(&out[base1 + pl]) = v1;
            }
        }
    }
}

// ---------------- host orchestration ----------------
extern "C" void kernel_launch(void* const* d_in, const int* in_sizes, int n_in,
                              void* d_out, int out_size)
{
    const float *x[4]={0,0,0,0}, *rx[4]={0,0,0,0};
    const float *wm[4]={0,0,0,0}, *bm[4]={0,0,0,0}, *wo[4]={0,0,0,0}, *bo[4]={0,0,0,0};
    int wmi = 0, woi = 0, bi = 0;
    for (int i = 0; i < n_in; i++){
        int s = in_sizes[i];
        int lvl = -1;
        if      (s == 2*256*128*128) lvl = 0;
        else if (s == 2*256*64*64)   lvl = 1;
        else if (s == 2*256*32*32)   lvl = 2;
        else if (s == 2*256*16*16)   lvl = 3;
        if (lvl >= 0){
            if (!x[lvl]) x[lvl] = (const float*)d_in[i];
            else         rx[lvl] = (const float*)d_in[i];
        }
        else if (s == 1845504) wm[wmi++] = (const float*)d_in[i];
        else if (s ==  589824) wo[woi++] = (const float*)d_in[i];
        else if (s ==     256){
            if ((bi & 1) == 0) bm[bi >> 1] = (const float*)d_in[i];
            else               bo[bi >> 1] = (const float*)d_in[i];
            bi++;
        }
    }

    float *corrB, *mapB;
    __nv_bfloat16 *wmh, *wml, *woh, *wol, *amh, *aml, *aoh, *aol;
    cudaGetSymbolAddress((void**)&corrB, g_corr);
    cudaGetSymbolAddress((void**)&mapB,  g_map);
    cudaGetSymbolAddress((void**)&wmh, g_wm_h); cudaGetSymbolAddress((void**)&wml, g_wm_l);
    cudaGetSymbolAddress((void**)&woh, g_wo_h); cudaGetSymbolAddress((void**)&wol, g_wo_l);
    cudaGetSymbolAddress((void**)&amh, g_am_h); cudaGetSymbolAddress((void**)&aml, g_am_l);
    cudaGetSymbolAddress((void**)&aoh, g_ao_h); cudaGetSymbolAddress((void**)&aol, g_ao_l);

    const int  Hl[4]      = {128, 64, 32, 16};
    const int  HWl[4]     = {16384, 4096, 1024, 256};
    const long corrOff[4] = {0, 9469952, 11837440, 12429312};
    const long mapOff[4]  = {0, 8388608, 10485760, 11010048};
    const long amOff[4]   = {0, 28121600, 35369984, 37293568};
    const long aoOff[4]   = {0, 8652800, 10883072, 11474944};
    const long wmOff[4]   = {0, 1916928, 3833856, 5750784};
    const long woOff[4]   = {0, 589824, 1179648, 1769472};
    const int  zmap[4]    = {1, 1, 3, 9};
    const int  zout[4]    = {1, 1, 3, 9};
    float* outp = (float*)d_out;

    // 1. pack weights
    for (int l = 0; l < 4; l++){
        k_pack_w<<<(256*832 + 255)/256, 256>>>(wm[l], wmh + wmOff[l], wml + wmOff[l], 801, 832);
        k_pack_w<<<(256*256 + 255)/256, 256>>>(wo[l], woh + woOff[l], wol + woOff[l], 256, 256);
    }

    // 2. correlation volumes
    for (int l = 0; l < 4; l++){
        int W = Hl[l];
        int groups = (W >= 32) ? 8 : 4;
        dim3 g(W / (groups * 4), Hl[l], 2);
        k_corr<<<g, groups * 17>>>(x[l], rx[l], corrB + corrOff[l], Hl[l], W, groups);
    }

    // 3. pack map activations (x | rx | corr -> padded NHWC bf16 hi/lo, Cpad=832)
    for (int l = 0; l < 4; l++){
        int H = Hl[l];
        int Np = 2 * (H + 2) * (H + 2);
        dim3 g((Np + 31) / 32, 832 / 32);
        k_pack_acts<<<g, dim3(32, 8)>>>(x[l], 256, rx[l], 256, corrB + corrOff[l], 289,
                                        amh + amOff[l], aml + amOff[l], H, H, 832);
    }

    // 4. map GEMMs (801 -> 256)
    for (int l = 0; l < 4; l++){
        int H = Hl[l];
        float* mout = mapB + mapOff[l];
        int total = 2 * 256 * HWl[l];
        int z = zmap[l];
        if (z > 1)
            k_init_bias<<<(total + 255)/256, 256>>>(mout, bm[l], HWl[l], total);
        dim3 g(2 * HWl[l] / 128, 2, z);
        k_gemm<<<g, 256>>>(wmh + wmOff[l], wml + wmOff[l],
                           amh + amOff[l], aml + amOff[l],
                           H, H, 832, 9 / z, mout, bm[l], z > 1 ? 1 : 0);
    }

    // 5. top-down upsample add
    for (int l = 3; l >= 1; l--){
        int total = 2 * 256 * HWl[l - 1];
        k_up_add<<<(total + 255)/256, 256>>>(mapB + mapOff[l - 1], mapB + mapOff[l],
                                             Hl[l - 1], Hl[l - 1], total);
    }

    // 6. pack out activations (map fp32 NCHW -> padded NHWC bf16 hi/lo, Cpad=256)
    for (int l = 0; l < 4; l++){
        int H = Hl[l];
        int Np = 2 * (H + 2) * (H + 2);
        dim3 g((Np + 31) / 32, 256 / 32);
        k_pack_acts<<<g, dim3(32, 8)>>>(mapB + mapOff[l], 256,
                                        (const float*)0, 0, (const float*)0, 0,
                                        aoh + aoOff[l], aol + aoOff[l], H, H, 256);
    }

    // 7. out GEMMs (256 -> 256) -> d_out
    for (int l = 0; l < 4; l++){
        int H = Hl[l];
        float* oo = outp + mapOff[l];
        int total = 2 * 256 * HWl[l];
        int z = zout[l];
        if (z > 1)
            k_init_bias<<<(total + 255)/256, 256>>>(oo, bo[l], HWl[l], total);
        dim3 g(2 * HWl[l] / 128, 2, z);
        k_gemm<<<g, 256>>>(woh + woOff[l], wol + woOff[l],
                           aoh + aoOff[l], aol + aoOff[l],
                           H, H, 256, 9 / z, oo, bo[l], z > 1 ? 1 : 0);
    }
}

// round 5
// speedup vs baseline: 1.5192x; 1.0677x over previous
#include <cuda_runtime.h>
#include <cuda_bf16.h>
#include <cstdint>
#include <cstddef>

#define PADC 8

// ---------------- static device buffers ----------------
__device__ __align__(256) float g_corr[12577280];
__device__ __align__(256) float g_map [11141120];
__device__ __align__(256) __nv_bfloat16 g_wm_h[7667712];   // [lvl][chunk26][tap9][co256][ci32] swizzled
__device__ __align__(256) __nv_bfloat16 g_wm_l[7667712];
__device__ __align__(256) __nv_bfloat16 g_wo_h[2359296];   // [lvl][chunk8][tap9][co256][ci32]
__device__ __align__(256) __nv_bfloat16 g_wo_l[2359296];
__device__ __align__(256) __nv_bfloat16 g_am_h[37832704];  // [lvl][chunk][b][Hp][Wp][32] swizzled
__device__ __align__(256) __nv_bfloat16 g_am_l[37832704];
__device__ __align__(256) __nv_bfloat16 g_ao_h[11640832];
__device__ __align__(256) __nv_bfloat16 g_ao_l[11640832];

// ---------------- PTX helpers (compute_103 baseline-safe) ----------------
__device__ __forceinline__ uint32_t smem_u32(const void* p){
    uint32_t a;
    asm("{ .reg .u64 t; cvta.to.shared.u64 t, %1; cvt.u32.u64 %0, t; }" : "=r"(a) : "l"(p));
    return a;
}
__device__ __forceinline__ void mbar_init(uint32_t a, uint32_t cnt){
    asm volatile("mbarrier.init.shared.b64 [%0], %1;" :: "r"(a), "r"(cnt) : "memory");
}
__device__ __forceinline__ void mbar_expect(uint32_t a, uint32_t bytes){
    asm volatile("mbarrier.arrive.expect_tx.shared.b64 _, [%0], %1;" :: "r"(a), "r"(bytes) : "memory");
}
__device__ __forceinline__ void mbar_wait(uint32_t a, int parity){
    asm volatile(
        "{\n\t.reg .pred P;\n\t"
        "WL_%=:\n\t"
        "mbarrier.try_wait.parity.acquire.cta.shared::cta.b64 P, [%0], %1, 0x989680;\n\t"
        "@P bra WD_%=;\n\t"
        "bra WL_%=;\n\t"
        "WD_%=:\n\t}"
        :: "r"(a), "r"(parity) : "memory");
}
__device__ __forceinline__ void bulk_cp(uint32_t dst, const void* src, uint32_t bytes, uint32_t mbar){
    asm volatile(
        "cp.async.bulk.shared::cluster.global.mbarrier::complete_tx::bytes [%0], [%1], %2, [%3];"
        :: "r"(dst), "l"(src), "r"(bytes), "r"(mbar) : "memory");
}
__device__ __forceinline__ void ldmx4(uint32_t* r, uint32_t addr){
    asm volatile("ldmatrix.sync.aligned.m8n8.x4.shared.b16 {%0,%1,%2,%3}, [%4];"
                 : "=r"(r[0]), "=r"(r[1]), "=r"(r[2]), "=r"(r[3]) : "r"(addr));
}
__device__ __forceinline__ void mma16816(float* c, const uint32_t* a, uint32_t b0, uint32_t b1){
    asm volatile(
        "mma.sync.aligned.m16n8k16.row.col.f32.bf16.bf16.f32 "
        "{%0,%1,%2,%3}, {%4,%5,%6,%7}, {%8,%9}, {%0,%1,%2,%3};"
        : "+f"(c[0]), "+f"(c[1]), "+f"(c[2]), "+f"(c[3])
        : "r"(a[0]), "r"(a[1]), "r"(a[2]), "r"(a[3]), "r"(b0), "r"(b1));
}

// ---------------- correlation (unchanged, validated) ----------------
__global__ void k_corr(const float* __restrict__ x, const float* __restrict__ ref,
                       float* __restrict__ corr, int H, int W, int groups){
    int g  = threadIdx.x % groups;
    int dy = threadIdx.x / groups;
    if (dy >= 17) return;
    int w0 = blockIdx.x * groups * 4;
    int h  = blockIdx.y;
    int b  = blockIdx.z;
    int wbase = w0 + g * 4;

    float acc[17][4];
    #pragma unroll
    for (int j = 0; j < 17; j++){ acc[j][0]=0.f; acc[j][1]=0.f; acc[j][2]=0.f; acc[j][3]=0.f; }

    int r = h + dy - PADC;
    int HW = H * W;
    if (r >= 0 && r < H){
        const float* xb = x   + ((b * 256) * H + h) * W;
        const float* rb = ref + ((b * 256) * H + r) * W;
        int q0 = wbase - PADC;
        bool interior = (q0 >= 0) && (q0 + 20 <= W);
        for (int c = 0; c < 256; c++){
            const float4 xv = *reinterpret_cast<const float4*>(xb + c * HW + wbase);
            const float* rr = rb + c * HW;
            float rv[20];
            if (interior){
                #pragma unroll
                for (int t = 0; t < 5; t++){
                    float4 v = *reinterpret_cast<const float4*>(rr + q0 + t * 4);
                    rv[t*4+0]=v.x; rv[t*4+1]=v.y; rv[t*4+2]=v.z; rv[t*4+3]=v.w;
                }
            } else {
                #pragma unroll
                for (int t = 0; t < 20; t++){
                    int q = q0 + t;
                    rv[t] = (q >= 0 && q < W) ? rr[q] : 0.f;
                }
            }
            #pragma unroll
            for (int j = 0; j < 17; j++){
                acc[j][0] += xv.x * rv[j];
                acc[j][1] += xv.y * rv[j+1];
                acc[j][2] += xv.z * rv[j+2];
                acc[j][3] += xv.w * rv[j+3];
            }
        }
    }
    #pragma unroll
    for (int j = 0; j < 17; j++){
        int d = dy * 17 + j;
        float4 o; o.x=acc[j][0]; o.y=acc[j][1]; o.z=acc[j][2]; o.w=acc[j][3];
        *reinterpret_cast<float4*>(corr + ((b * 289 + d) * H + h) * W + wbase) = o;
    }
}

// ---------------- misc small kernels ----------------
__global__ void k_init_bias(float* __restrict__ out, const float* __restrict__ bias,
                            int HW, int total){
    int i = blockIdx.x * blockDim.x + threadIdx.x;
    if (i < total) out[i] = bias[(i / HW) & 255];
}
__global__ void k_up_add(float* __restrict__ dst, const float* __restrict__ src,
                         int H, int W, int total){
    int i = blockIdx.x * blockDim.x + threadIdx.x;
    if (i >= total) return;
    int w = i % W; int t = i / W; int h = t % H; int bc = t / H;
    dst[i] += src[(bc * (H >> 1) + (h >> 1)) * (W >> 1) + (w >> 1)];
}

// ---------------- weight pack: w[co][ci][3][3] -> [chunk][tap][co][32ci] swizzled ----------------
__global__ void k_pack_w(const float* __restrict__ w, __nv_bfloat16* __restrict__ oh,
                         __nv_bfloat16* __restrict__ ol, int Cin, int Cpad){
    int i = blockIdx.x * 256 + threadIdx.x;
    if (i >= 256 * Cpad) return;
    int co = i / Cpad, ci = i % Cpad;
    int c = ci >> 5, cl = ci & 31;
    int gsw = (cl >> 3) ^ ((co >> 1) & 3);
    #pragma unroll
    for (int t = 0; t < 9; t++){
        float v = (ci < Cin) ? w[(size_t)(co * Cin + ci) * 9 + t] : 0.f;
        __nv_bfloat16 h = __float2bfloat16(v);
        float l = v - __bfloat162float(h);
        size_t o = (((size_t)c * 9 + t) * 256 + co) * 32 + (gsw << 3) + (cl & 7);
        oh[o] = h;
        ol[o] = __float2bfloat16(l);
    }
}

// ---------------- act pack: NCHW fp32 -> [chunk][b][Hp][Wp][32] bf16 hi/lo, swizzled ----------------
__global__ void k_pack_acts(const float* __restrict__ S0, int C0,
                            const float* __restrict__ S1, int C1,
                            const float* __restrict__ S2, int C2,
                            __nv_bfloat16* __restrict__ Ph, __nv_bfloat16* __restrict__ Pl,
                            int H, int W, int Cpad){
    __shared__ float t[32][33];
    int Hp = H + 2, Wp = W + 2, HW = H * W, Np = 2 * Hp * Wp;
    int p0 = blockIdx.x * 32, c0 = blockIdx.y * 32;
    int px = p0 + threadIdx.x;
    int b = 0, pix = 0; bool inter = false;
    if (px < Np){
        b = px / (Hp * Wp); int r = px % (Hp * Wp); int hp = r / Wp, wp = r % Wp;
        if (hp >= 1 && hp <= H && wp >= 1 && wp <= W){ inter = true; pix = (hp - 1) * W + (wp - 1); }
    }
    #pragma unroll
    for (int dyy = 0; dyy < 32; dyy += 8){
        int ci = c0 + (int)threadIdx.y + dyy;
        float v = 0.f;
        if (inter){
            if (ci < C0)                 v = S0[(size_t)(b * C0 + ci) * HW + pix];
            else if (ci < C0 + C1)       v = S1[(size_t)(b * C1 + ci - C0) * HW + pix];
            else if (ci < C0 + C1 + C2)  v = S2[(size_t)(b * C2 + (ci - C0 - C1)) * HW + pix];
        }
        t[threadIdx.y + dyy][threadIdx.x] = v;
    }
    __syncthreads();
    int ft = threadIdx.y * 32 + threadIdx.x;
    int pl = ft >> 3, sub = ft & 7;
    int px2 = p0 + pl;
    if (px2 < Np){
        size_t chStride = (size_t)2 * Hp * Wp * 32;
        int gsw = (sub >> 1) ^ ((px2 >> 1) & 3);
        size_t base = (size_t)(c0 >> 5) * chStride + (size_t)px2 * 32 + (gsw << 3) + (sub & 1) * 4;
        float v0 = t[sub*4+0][pl], v1 = t[sub*4+1][pl], v2 = t[sub*4+2][pl], v3 = t[sub*4+3][pl];
        __nv_bfloat16 h0 = __float2bfloat16(v0), h1 = __float2bfloat16(v1);
        __nv_bfloat16 h2 = __float2bfloat16(v2), h3 = __float2bfloat16(v3);
        uint32_t uh0 = (uint32_t)__bfloat16_as_ushort(h0) | ((uint32_t)__bfloat16_as_ushort(h1) << 16);
        uint32_t uh1 = (uint32_t)__bfloat16_as_ushort(h2) | ((uint32_t)__bfloat16_as_ushort(h3) << 16);
        uint2 wh; wh.x = uh0; wh.y = uh1;
        *reinterpret_cast<uint2*>(Ph + base) = wh;
        __nv_bfloat16 l0 = __float2bfloat16(v0 - __bfloat162float(h0));
        __nv_bfloat16 l1 = __float2bfloat16(v1 - __bfloat162float(h1));
        __nv_bfloat16 l2 = __float2bfloat16(v2 - __bfloat162float(h2));
        __nv_bfloat16 l3 = __float2bfloat16(v3 - __bfloat162float(h3));
        uint32_t ul0 = (uint32_t)__bfloat16_as_ushort(l0) | ((uint32_t)__bfloat16_as_ushort(l1) << 16);
        uint32_t ul1 = (uint32_t)__bfloat16_as_ushort(l2) | ((uint32_t)__bfloat16_as_ushort(l3) << 16);
        uint2 wl; wl.x = ul0; wl.y = ul1;
        *reinterpret_cast<uint2*>(Pl + base) = wl;
    }
}

// ---------------- bulk-copy pipelined implicit-conv GEMM ----------------
// CTA: 128 co x 256 px. B smem = (R+2)x(W+2)x32ci halo region, serves all 9 taps.
// A smem = 128co x 32ci per (chunk,tap). Double-buffered via cp.async.bulk + mbarrier.
__global__ __launch_bounds__(256)
void k_gemm(const __nv_bfloat16* __restrict__ Ah, const __nv_bfloat16* __restrict__ Al,
            const __nv_bfloat16* __restrict__ Bh, const __nv_bfloat16* __restrict__ Bl,
            int H, int W, int lgW, int CH, int tapsPerZ,
            float* __restrict__ out, const float* __restrict__ bias, int useAtomic)
{
    extern __shared__ char dsm[];
    __shared__ __align__(8) unsigned long long mb[4];

    const uint32_t smemBase = smem_u32(dsm);
    const uint32_t A_OFF[2] = {smemBase, smemBase + 8192u};
    const uint32_t B_OFF[2] = {smemBase + 16384u, smemBase + 16384u + 33280u};
    const uint32_t MBA[2] = {smem_u32(&mb[0]), smem_u32(&mb[1])};
    const uint32_t MBB[2] = {smem_u32(&mb[2]), smem_u32(&mb[3])};

    const int tid = threadIdx.x, wid = tid >> 5, lane = tid & 31;
    const int R = 256 >> lgW;
    const int Hp = H + 2, Wp = W + 2;
    const int tilesPerB = H / R;
    const int b  = blockIdx.x / tilesPerB;
    const int h0 = (blockIdx.x % tilesPerB) * R;
    const int m0 = blockIdx.y * 128;
    const int tapBeg = blockIdx.z * tapsPerZ;
    const int q0 = (b * Hp + h0) * Wp;
    const uint32_t Bbytes = (uint32_t)(R + 2) * Wp * 64u;
    const size_t chStride = (size_t)2 * Hp * Wp * 32;

    if (tid == 0){
        #pragma unroll
        for (int i = 0; i < 4; i++) mbar_init(MBA[0] + i * 8, 1);
    }
    __syncthreads();

    const int nB = 3 * CH;
    const int nA = nB * tapsPerZ;

    auto issueA = [&](int ia){
        int tap = ia % tapsPerZ;
        int ibb = ia / tapsPerZ;
        int pass = ibb / CH, c = ibb % CH;
        const __nv_bfloat16* src = ((pass == 2) ? Al : Ah)
            + ((((size_t)c * 9 + (tapBeg + tap)) * 256 + m0) << 5);
        int s = ia & 1;
        mbar_expect(MBA[s], 8192u);
        bulk_cp(A_OFF[s], src, 8192u, MBA[s]);
    };
    auto issueB = [&](int ib){
        int pass = ib / CH, c = ib % CH;
        const __nv_bfloat16* src = ((pass == 1) ? Bl : Bh) + (size_t)c * chStride + ((size_t)q0 << 5);
        int s = ib & 1;
        mbar_expect(MBB[s], Bbytes);
        bulk_cp(B_OFF[s], src, Bbytes, MBB[s]);
    };

    // lane constants
    const int lr  = lane & 7;
    const int lm8 = ((lane >> 3) & 1) * 8;
    const int lk  = lane >> 4;
    const int wm  = wid & 1;      // 2 m-subtiles of 64 co
    const int wn  = wid >> 1;     // 4 n-subtiles of 64 px
    const int rowA = wm * 64 + lm8 + lr;
    const int xorA = (lr >> 1) & 3;
    int rB[4], wB[4];
    #pragma unroll
    for (int g = 0; g < 4; g++){
        int n = wn * 64 + g * 16 + lm8 + lr;
        rB[g] = n >> lgW;
        wB[g] = n & (W - 1);
    }

    float acc[4][8][4];
    #pragma unroll
    for (int i = 0; i < 4; i++)
        #pragma unroll
        for (int j = 0; j < 8; j++)
            #pragma unroll
            for (int k = 0; k < 4; k++) acc[i][j][k] = 0.f;

    if (tid == 0){ issueA(0); issueB(0); }

    for (int it = 0; it < nA; ++it){
        int tap = it % tapsPerZ;
        int ibb = it / tapsPerZ;
        if (tid == 0){
            if (it + 1 < nA) issueA(it + 1);
            if (tap == 0 && ibb + 1 < nB) issueB(ibb + 1);
        }
        mbar_wait(MBA[it & 1], (it >> 1) & 1);
        if (tap == 0) mbar_wait(MBB[ibb & 1], (ibb >> 1) & 1);

        const uint32_t Ab = A_OFF[it & 1];
        const uint32_t Bb = B_OFF[ibb & 1];
        const int tIdx = tapBeg + tap;
        const int dy = tIdx / 3, dx = tIdx - dy * 3;

        uint32_t sAdr[4]; int xorB[4];
        #pragma unroll
        for (int g = 0; g < 4; g++){
            int s = (rB[g] + dy) * Wp + wB[g] + dx;
            sAdr[g] = Bb + (uint32_t)s * 64u;
            xorB[g] = ((q0 + s) >> 1) & 3;
        }

        #pragma unroll
        for (int ks = 0; ks < 2; ks++){
            const int gA = (2 * ks + lk) ^ xorA;
            uint32_t a[4][4];
            #pragma unroll
            for (int ma = 0; ma < 4; ma++)
                ldmx4(a[ma], Ab + (uint32_t)(rowA + ma * 16) * 64u + ((uint32_t)gA << 4));
            uint32_t bb[4][4];
            #pragma unroll
            for (int g = 0; g < 4; g++){
                int gB = (2 * ks + lk) ^ xorB[g];
                ldmx4(bb[g], sAdr[g] + ((uint32_t)gB << 4));
            }
            #pragma unroll
            for (int ma = 0; ma < 4; ma++)
                #pragma unroll
                for (int na = 0; na < 8; na++)
                    mma16816(acc[ma][na], a[ma], bb[na >> 1][na & 1], bb[na >> 1][2 + (na & 1)]);
        }
        __syncthreads();
    }

    // epilogue: NCHW
    #pragma unroll
    for (int ma = 0; ma < 4; ma++){
        int co0 = m0 + wm * 64 + ma * 16 + (lane >> 2);
        int co1 = co0 + 8;
        float bv0 = useAtomic ? 0.f : bias[co0];
        float bv1 = useAtomic ? 0.f : bias[co1];
        #pragma unroll
        for (int na = 0; na < 8; na++){
            int n = wn * 64 + na * 8 + (lane & 3) * 2;
            int r = h0 + (n >> lgW);
            int w = n & (W - 1);
            size_t i0 = ((size_t)(b * 256 + co0) * H + r) * W + w;
            size_t i1 = ((size_t)(b * 256 + co1) * H + r) * W + w;
            if (useAtomic){
                atomicAdd(&out[i0],     acc[ma][na][0]);
                atomicAdd(&out[i0 + 1], acc[ma][na][1]);
                atomicAdd(&out[i1],     acc[ma][na][2]);
                atomicAdd(&out[i1 + 1], acc[ma][na][3]);
            } else {
                float2 v0; v0.x = acc[ma][na][0] + bv0; v0.y = acc[ma][na][1] + bv0;
                float2 v1; v1.x = acc[ma][na][2] + bv1; v1.y = acc[ma][na][3] + bv1;
                *reinterpret_cast<float2*>(&out[i0]) = v0;
                *reinterpret_cast<float2*>(&out[i1]) = v1;
            }
        }
    }
}

// ---------------- host orchestration ----------------
extern "C" void kernel_launch(void* const* d_in, const int* in_sizes, int n_in,
                              void* d_out, int out_size)
{
    const float *x[4]={0,0,0,0}, *rx[4]={0,0,0,0};
    const float *wm[4]={0,0,0,0}, *bm[4]={0,0,0,0}, *wo[4]={0,0,0,0}, *bo[4]={0,0,0,0};
    int wmi = 0, woi = 0, bi = 0;
    for (int i = 0; i < n_in; i++){
        int s = in_sizes[i];
        int lvl = -1;
        if      (s == 2*256*128*128) lvl = 0;
        else if (s == 2*256*64*64)   lvl = 1;
        else if (s == 2*256*32*32)   lvl = 2;
        else if (s == 2*256*16*16)   lvl = 3;
        if (lvl >= 0){
            if (!x[lvl]) x[lvl] = (const float*)d_in[i];
            else         rx[lvl] = (const float*)d_in[i];
        }
        else if (s == 1845504) wm[wmi++] = (const float*)d_in[i];
        else if (s ==  589824) wo[woi++] = (const float*)d_in[i];
        else if (s ==     256){
            if ((bi & 1) == 0) bm[bi >> 1] = (const float*)d_in[i];
            else               bo[bi >> 1] = (const float*)d_in[i];
            bi++;
        }
    }

    float *corrB, *mapB;
    __nv_bfloat16 *wmh, *wml, *woh, *wol, *amh, *aml, *aoh, *aol;
    cudaGetSymbolAddress((void**)&corrB, g_corr);
    cudaGetSymbolAddress((void**)&mapB,  g_map);
    cudaGetSymbolAddress((void**)&wmh, g_wm_h); cudaGetSymbolAddress((void**)&wml, g_wm_l);
    cudaGetSymbolAddress((void**)&woh, g_wo_h); cudaGetSymbolAddress((void**)&wol, g_wo_l);
    cudaGetSymbolAddress((void**)&amh, g_am_h); cudaGetSymbolAddress((void**)&aml, g_am_l);
    cudaGetSymbolAddress((void**)&aoh, g_ao_h); cudaGetSymbolAddress((void**)&aol, g_ao_l);

    cudaFuncSetAttribute(k_gemm, cudaFuncAttributeMaxDynamicSharedMemorySize, 82944);

    const int  Hl[4]      = {128, 64, 32, 16};
    const int  lgWl[4]    = {7, 6, 5, 4};
    const int  HWl[4]     = {16384, 4096, 1024, 256};
    const long corrOff[4] = {0, 9469952, 11837440, 12429312};
    const long mapOff[4]  = {0, 8388608, 10485760, 11010048};
    const long amOff[4]   = {0, 28121600, 35369984, 37293568};
    const long aoOff[4]   = {0, 8652800, 10883072, 11474944};
    const long wmOff[4]   = {0, 1916928, 3833856, 5750784};
    const long woOff[4]   = {0, 589824, 1179648, 1769472};
    const int  zmap[4]    = {1, 3, 9, 9};
    const int  zout[4]    = {1, 3, 9, 9};
    float* outp = (float*)d_out;

    // 1. pack weights (chunk-major + swizzle)
    for (int l = 0; l < 4; l++){
        k_pack_w<<<(256*832 + 255)/256, 256>>>(wm[l], wmh + wmOff[l], wml + wmOff[l], 801, 832);
        k_pack_w<<<(256*256 + 255)/256, 256>>>(wo[l], woh + woOff[l], wol + woOff[l], 256, 256);
    }

    // 2. correlation volumes
    for (int l = 0; l < 4; l++){
        int W = Hl[l];
        int groups = (W >= 32) ? 8 : 4;
        dim3 g(W / (groups * 4), Hl[l], 2);
        k_corr<<<g, groups * 17>>>(x[l], rx[l], corrB + corrOff[l], Hl[l], W, groups);
    }

    // 3. pack map activations
    for (int l = 0; l < 4; l++){
        int H = Hl[l];
        int Np = 2 * (H + 2) * (H + 2);
        dim3 g((Np + 31) / 32, 832 / 32);
        k_pack_acts<<<g, dim3(32, 8)>>>(x[l], 256, rx[l], 256, corrB + corrOff[l], 289,
                                        amh + amOff[l], aml + amOff[l], H, H, 832);
    }

    // 4. map GEMMs (801 -> 256)
    for (int l = 0; l < 4; l++){
        int H = Hl[l];
        float* mout = mapB + mapOff[l];
        int total = 2 * 256 * HWl[l];
        int z = zmap[l];
        if (z > 1)
            k_init_bias<<<(total + 255)/256, 256>>>(mout, bm[l], HWl[l], total);
        dim3 g(2 * HWl[l] / 256, 2, z);
        k_gemm<<<g, 256, 82944>>>(wmh + wmOff[l], wml + wmOff[l],
                                  amh + amOff[l], aml + amOff[l],
                                  H, H, lgWl[l], 26, 9 / z, mout, bm[l], z > 1 ? 1 : 0);
    }

    // 5. top-down upsample add
    for (int l = 3; l >= 1; l--){
        int total = 2 * 256 * HWl[l - 1];
        k_up_add<<<(total + 255)/256, 256>>>(mapB + mapOff[l - 1], mapB + mapOff[l],
                                             Hl[l - 1], Hl[l - 1], total);
    }

    // 6. pack out activations
    for (int l = 0; l < 4; l++){
        int H = Hl[l];
        int Np = 2 * (H + 2) * (H + 2);
        dim3 g((Np + 31) / 32, 256 / 32);
        k_pack_acts<<<g, dim3(32, 8)>>>(mapB + mapOff[l], 256,
                                        (const float*)0, 0, (const float*)0, 0,
                                        aoh + aoOff[l], aol + aoOff[l], H, H, 256);
    }

    // 7. out GEMMs (256 -> 256) -> d_out
    for (int l = 0; l < 4; l++){
        int H = Hl[l];
        float* oo = outp + mapOff[l];
        int total = 2 * 256 * HWl[l];
        int z = zout[l];
        if (z > 1)
            k_init_bias<<<(total + 255)/256, 256>>>(oo, bo[l], HWl[l], total);
        dim3 g(2 * HWl[l] / 256, 2, z);
        k_gemm<<<g, 256, 82944>>>(woh + woOff[l], wol + woOff[l],
                                  aoh + aoOff[l], aol + aoOff[l],
                                  H, H, lgWl[l], 8, 9 / z, oo, bo[l], z > 1 ? 1 : 0);
    }
}

// round 6
// speedup vs baseline: 2.3101x; 1.5206x over previous
#include <cuda_runtime.h>
#include <cuda_fp16.h>
#include <cstdint>
#include <cstddef>

#define PADC 8

// ---------------- static device buffers ----------------
__device__ __align__(256) float g_corr[12577280];
__device__ __align__(256) float g_map [11141120];
__device__ __align__(256) __half g_wm_h[7667712];   // [lvl][chunk26][tap9][co256][ci32] swizzled
__device__ __align__(256) __half g_wo_h[2359296];   // [lvl][chunk8][tap9][co256][ci32]
__device__ __align__(256) __half g_am_h[37832704];  // [lvl][chunk][b][Hp][Wp][32] swizzled
__device__ __align__(256) __half g_am_l[37832704];
__device__ __align__(256) __half g_ao_h[11640832];
__device__ __align__(256) __half g_ao_l[11640832];

// ---------------- PTX helpers (compute_103 baseline-safe) ----------------
__device__ __forceinline__ uint32_t smem_u32(const void* p){
    uint32_t a;
    asm("{ .reg .u64 t; cvta.to.shared.u64 t, %1; cvt.u32.u64 %0, t; }" : "=r"(a) : "l"(p));
    return a;
}
__device__ __forceinline__ void mbar_init(uint32_t a, uint32_t cnt){
    asm volatile("mbarrier.init.shared.b64 [%0], %1;" :: "r"(a), "r"(cnt) : "memory");
}
__device__ __forceinline__ void mbar_expect(uint32_t a, uint32_t bytes){
    asm volatile("mbarrier.arrive.expect_tx.shared.b64 _, [%0], %1;" :: "r"(a), "r"(bytes) : "memory");
}
__device__ __forceinline__ void mbar_wait(uint32_t a, int parity){
    asm volatile(
        "{\n\t.reg .pred P;\n\t"
        "WL_%=:\n\t"
        "mbarrier.try_wait.parity.acquire.cta.shared::cta.b64 P, [%0], %1, 0x989680;\n\t"
        "@P bra WD_%=;\n\t"
        "bra WL_%=;\n\t"
        "WD_%=:\n\t}"
        :: "r"(a), "r"(parity) : "memory");
}
__device__ __forceinline__ void bulk_cp(uint32_t dst, const void* src, uint32_t bytes, uint32_t mbar){
    asm volatile(
        "cp.async.bulk.shared::cluster.global.mbarrier::complete_tx::bytes [%0], [%1], %2, [%3];"
        :: "r"(dst), "l"(src), "r"(bytes), "r"(mbar) : "memory");
}
__device__ __forceinline__ void ldmx4(uint32_t* r, uint32_t addr){
    asm volatile("ldmatrix.sync.aligned.m8n8.x4.shared.b16 {%0,%1,%2,%3}, [%4];"
                 : "=r"(r[0]), "=r"(r[1]), "=r"(r[2]), "=r"(r[3]) : "r"(addr));
}
__device__ __forceinline__ void mma16816(float* c, const uint32_t* a, uint32_t b0, uint32_t b1){
    asm volatile(
        "mma.sync.aligned.m16n8k16.row.col.f32.f16.f16.f32 "
        "{%0,%1,%2,%3}, {%4,%5,%6,%7}, {%8,%9}, {%0,%1,%2,%3};"
        : "+f"(c[0]), "+f"(c[1]), "+f"(c[2]), "+f"(c[3])
        : "r"(a[0]), "r"(a[1]), "r"(a[2]), "r"(a[3]), "r"(b0), "r"(b1));
}

// ---------------- correlation (unchanged, validated) ----------------
__global__ void k_corr(const float* __restrict__ x, const float* __restrict__ ref,
                       float* __restrict__ corr, int H, int W, int groups){
    int g  = threadIdx.x % groups;
    int dy = threadIdx.x / groups;
    if (dy >= 17) return;
    int w0 = blockIdx.x * groups * 4;
    int h  = blockIdx.y;
    int b  = blockIdx.z;
    int wbase = w0 + g * 4;

    float acc[17][4];
    #pragma unroll
    for (int j = 0; j < 17; j++){ acc[j][0]=0.f; acc[j][1]=0.f; acc[j][2]=0.f; acc[j][3]=0.f; }

    int r = h + dy - PADC;
    int HW = H * W;
    if (r >= 0 && r < H){
        const float* xb = x   + ((b * 256) * H + h) * W;
        const float* rb = ref + ((b * 256) * H + r) * W;
        int q0 = wbase - PADC;
        bool interior = (q0 >= 0) && (q0 + 20 <= W);
        for (int c = 0; c < 256; c++){
            const float4 xv = *reinterpret_cast<const float4*>(xb + c * HW + wbase);
            const float* rr = rb + c * HW;
            float rv[20];
            if (interior){
                #pragma unroll
                for (int t = 0; t < 5; t++){
                    float4 v = *reinterpret_cast<const float4*>(rr + q0 + t * 4);
                    rv[t*4+0]=v.x; rv[t*4+1]=v.y; rv[t*4+2]=v.z; rv[t*4+3]=v.w;
                }
            } else {
                #pragma unroll
                for (int t = 0; t < 20; t++){
                    int q = q0 + t;
                    rv[t] = (q >= 0 && q < W) ? rr[q] : 0.f;
                }
            }
            #pragma unroll
            for (int j = 0; j < 17; j++){
                acc[j][0] += xv.x * rv[j];
                acc[j][1] += xv.y * rv[j+1];
                acc[j][2] += xv.z * rv[j+2];
                acc[j][3] += xv.w * rv[j+3];
            }
        }
    }
    #pragma unroll
    for (int j = 0; j < 17; j++){
        int d = dy * 17 + j;
        float4 o; o.x=acc[j][0]; o.y=acc[j][1]; o.z=acc[j][2]; o.w=acc[j][3];
        *reinterpret_cast<float4*>(corr + ((b * 289 + d) * H + h) * W + wbase) = o;
    }
}

// ---------------- misc small kernels ----------------
__global__ void k_init_bias(float* __restrict__ out, const float* __restrict__ bias,
                            int HW, int total){
    int i = blockIdx.x * blockDim.x + threadIdx.x;
    if (i < total) out[i] = bias[(i / HW) & 255];
}
__global__ void k_up_add(float* __restrict__ dst, const float* __restrict__ src,
                         int H, int W, int total){
    int i = blockIdx.x * blockDim.x + threadIdx.x;
    if (i >= total) return;
    int w = i % W; int t = i / W; int h = t % H; int bc = t / H;
    dst[i] += src[(bc * (H >> 1) + (h >> 1)) * (W >> 1) + (w >> 1)];
}

// ---------------- weight pack: w[co][ci][3][3] -> [chunk][tap][co][32ci] swizzled (fp16 hi only) ----------------
__global__ void k_pack_w(const float* __restrict__ w, __half* __restrict__ oh,
                         int Cin, int Cpad){
    int i = blockIdx.x * 256 + threadIdx.x;
    if (i >= 256 * Cpad) return;
    int co = i / Cpad, ci = i % Cpad;
    int c = ci >> 5, cl = ci & 31;
    int gsw = (cl >> 3) ^ ((co >> 1) & 3);
    #pragma unroll
    for (int t = 0; t < 9; t++){
        float v = (ci < Cin) ? w[(size_t)(co * Cin + ci) * 9 + t] : 0.f;
        size_t o = (((size_t)c * 9 + t) * 256 + co) * 32 + (gsw << 3) + (cl & 7);
        oh[o] = __float2half_rn(v);
    }
}

// ---------------- act pack: NCHW fp32 -> [chunk][b][Hp][Wp][32] fp16 hi/lo, swizzled ----------------
__global__ void k_pack_acts(const float* __restrict__ S0, int C0,
                            const float* __restrict__ S1, int C1,
                            const float* __restrict__ S2, int C2,
                            __half* __restrict__ Ph, __half* __restrict__ Pl,
                            int H, int W, int Cpad){
    __shared__ float t[32][33];
    int Hp = H + 2, Wp = W + 2, HW = H * W, Np = 2 * Hp * Wp;
    int p0 = blockIdx.x * 32, c0 = blockIdx.y * 32;
    int px = p0 + threadIdx.x;
    int b = 0, pix = 0; bool inter = false;
    if (px < Np){
        b = px / (Hp * Wp); int r = px % (Hp * Wp); int hp = r / Wp, wp = r % Wp;
        if (hp >= 1 && hp <= H && wp >= 1 && wp <= W){ inter = true; pix = (hp - 1) * W + (wp - 1); }
    }
    #pragma unroll
    for (int dyy = 0; dyy < 32; dyy += 8){
        int ci = c0 + (int)threadIdx.y + dyy;
        float v = 0.f;
        if (inter){
            if (ci < C0)                 v = S0[(size_t)(b * C0 + ci) * HW + pix];
            else if (ci < C0 + C1)       v = S1[(size_t)(b * C1 + ci - C0) * HW + pix];
            else if (ci < C0 + C1 + C2)  v = S2[(size_t)(b * C2 + (ci - C0 - C1)) * HW + pix];
        }
        t[threadIdx.y + dyy][threadIdx.x] = v;
    }
    __syncthreads();
    int ft = threadIdx.y * 32 + threadIdx.x;
    int pl = ft >> 3, sub = ft & 7;
    int px2 = p0 + pl;
    if (px2 < Np){
        size_t chStride = (size_t)2 * Hp * Wp * 32;
        int gsw = (sub >> 1) ^ ((px2 >> 1) & 3);
        size_t base = (size_t)(c0 >> 5) * chStride + (size_t)px2 * 32 + (gsw << 3) + (sub & 1) * 4;
        float v0 = t[sub*4+0][pl], v1 = t[sub*4+1][pl], v2 = t[sub*4+2][pl], v3 = t[sub*4+3][pl];
        __half h0 = __float2half_rn(v0), h1 = __float2half_rn(v1);
        __half h2 = __float2half_rn(v2), h3 = __float2half_rn(v3);
        uint32_t uh0 = (uint32_t)__half_as_ushort(h0) | ((uint32_t)__half_as_ushort(h1) << 16);
        uint32_t uh1 = (uint32_t)__half_as_ushort(h2) | ((uint32_t)__half_as_ushort(h3) << 16);
        uint2 wh; wh.x = uh0; wh.y = uh1;
        *reinterpret_cast<uint2*>(Ph + base) = wh;
        __half l0 = __float2half_rn(v0 - __half2float(h0));
        __half l1 = __float2half_rn(v1 - __half2float(h1));
        __half l2 = __float2half_rn(v2 - __half2float(h2));
        __half l3 = __float2half_rn(v3 - __half2float(h3));
        uint32_t ul0 = (uint32_t)__half_as_ushort(l0) | ((uint32_t)__half_as_ushort(l1) << 16);
        uint32_t ul1 = (uint32_t)__half_as_ushort(l2) | ((uint32_t)__half_as_ushort(l3) << 16);
        uint2 wl; wl.x = ul0; wl.y = ul1;
        *reinterpret_cast<uint2*>(Pl + base) = wl;
    }
}

// ---------------- fp16 2-pass pipelined implicit-conv GEMM ----------------
// CTA: 128 co x 256 px. Per chunk c: B stage holds {Bh, Bl} halo pair (serves 9 taps x 2 passes).
// A (weights, fp16 hi only) 4-stage pipeline, one tile per (chunk, tap), reused across both passes.
__global__ __launch_bounds__(256)
void k_gemm(const __half* __restrict__ A,
            const __half* __restrict__ Bh, const __half* __restrict__ Bl,
            int H, int W, int lgW, int CH, int tapsPerZ,
            float* __restrict__ out, const float* __restrict__ bias, int useAtomic)
{
    extern __shared__ char dsm[];
    __shared__ __align__(8) unsigned long long mb[6];

    const uint32_t smemBase = smem_u32(dsm);
    uint32_t A_OFF[4], B_OFF[2];
    #pragma unroll
    for (int s = 0; s < 4; s++) A_OFF[s] = smemBase + s * 8192u;
    B_OFF[0] = smemBase + 32768u;
    B_OFF[1] = smemBase + 32768u + 66560u;
    const uint32_t MBA = smem_u32(&mb[0]);   // 4 mbars
    const uint32_t MBB = smem_u32(&mb[4]);   // 2 mbars

    const int tid = threadIdx.x, wid = tid >> 5, lane = tid & 31;
    const int R = 256 >> lgW;
    const int Hp = H + 2, Wp = W + 2;
    const int tilesPerB = H / R;
    const int b  = blockIdx.x / tilesPerB;
    const int h0 = (blockIdx.x % tilesPerB) * R;
    const int m0 = blockIdx.y * 128;
    const int tapBeg = blockIdx.z * tapsPerZ;
    const int q0 = (b * Hp + h0) * Wp;
    const uint32_t Bbytes = (uint32_t)(R + 2) * Wp * 64u;
    const size_t chStride = (size_t)2 * Hp * Wp * 32;

    if (tid == 0){
        #pragma unroll
        for (int i = 0; i < 6; i++) mbar_init(MBA + i * 8, 1);
    }
    __syncthreads();

    const int nA = CH * tapsPerZ;

    auto issueA = [&](int ia){
        int c = ia / tapsPerZ, tap = ia % tapsPerZ;
        const __half* src = A + ((((size_t)c * 9 + (tapBeg + tap)) * 256 + m0) << 5);
        int s = ia & 3;
        mbar_expect(MBA + s * 8, 8192u);
        bulk_cp(A_OFF[s], src, 8192u, MBA + s * 8);
    };
    auto issueB = [&](int c){
        int s = c & 1;
        mbar_expect(MBB + s * 8, 2u * Bbytes);
        bulk_cp(B_OFF[s],          Bh + (size_t)c * chStride + ((size_t)q0 << 5), Bbytes, MBB + s * 8);
        bulk_cp(B_OFF[s] + 33280u, Bl + (size_t)c * chStride + ((size_t)q0 << 5), Bbytes, MBB + s * 8);
    };

    // lane constants
    const int lr  = lane & 7;
    const int lm8 = ((lane >> 3) & 1) * 8;
    const int lk  = lane >> 4;
    const int wm  = wid & 1;      // 2 m-subtiles of 64 co
    const int wn  = wid >> 1;     // 4 n-subtiles of 64 px
    const int rowA = wm * 64 + lm8 + lr;
    const int xorA = (lr >> 1) & 3;
    int rB[4], wB[4];
    #pragma unroll
    for (int g = 0; g < 4; g++){
        int n = wn * 64 + g * 16 + lm8 + lr;
        rB[g] = n >> lgW;
        wB[g] = n & (W - 1);
    }

    float acc[4][8][4];
    #pragma unroll
    for (int i = 0; i < 4; i++)
        #pragma unroll
        for (int j = 0; j < 8; j++)
            #pragma unroll
            for (int k = 0; k < 4; k++) acc[i][j][k] = 0.f;

    if (tid == 0){
        issueB(0);
        issueA(0);
        if (nA > 1) issueA(1);
        if (nA > 2) issueA(2);
    }

    for (int it = 0; it < nA; ++it){
        int c = it / tapsPerZ, tap = it % tapsPerZ;
        if (tid == 0){
            if (it + 3 < nA) issueA(it + 3);
            if (tap == 0 && c + 1 < CH) issueB(c + 1);
        }
        mbar_wait(MBA + (it & 3) * 8, (it >> 2) & 1);
        if (tap == 0) mbar_wait(MBB + (c & 1) * 8, (c >> 1) & 1);

        const uint32_t Ab = A_OFF[it & 3];
        const uint32_t Bb = B_OFF[c & 1];
        const int tIdx = tapBeg + tap;
        const int dy = tIdx / 3, dx = tIdx - dy * 3;

        uint32_t sAdr[4]; int xorB[4];
        #pragma unroll
        for (int g = 0; g < 4; g++){
            int s = (rB[g] + dy) * Wp + wB[g] + dx;
            sAdr[g] = Bb + (uint32_t)s * 64u;
            xorB[g] = ((q0 + s) >> 1) & 3;
        }

        #pragma unroll
        for (int ks = 0; ks < 2; ks++){
            const int gA = (2 * ks + lk) ^ xorA;
            uint32_t a[4][4];
            #pragma unroll
            for (int ma = 0; ma < 4; ma++)
                ldmx4(a[ma], Ab + (uint32_t)(rowA + ma * 16) * 64u + ((uint32_t)gA << 4));
            #pragma unroll
            for (int pass = 0; pass < 2; pass++){
                uint32_t bb[4][4];
                #pragma unroll
                for (int g = 0; g < 4; g++){
                    int gB = (2 * ks + lk) ^ xorB[g];
                    ldmx4(bb[g], sAdr[g] + (uint32_t)pass * 33280u + ((uint32_t)gB << 4));
                }
                #pragma unroll
                for (int ma = 0; ma < 4; ma++)
                    #pragma unroll
                    for (int na = 0; na < 8; na++)
                        mma16816(acc[ma][na], a[ma], bb[na >> 1][na & 1], bb[na >> 1][2 + (na & 1)]);
            }
        }
        __syncthreads();
    }

    // epilogue: NCHW
    #pragma unroll
    for (int ma = 0; ma < 4; ma++){
        int co0 = m0 + wm * 64 + ma * 16 + (lane >> 2);
        int co1 = co0 + 8;
        float bv0 = useAtomic ? 0.f : bias[co0];
        float bv1 = useAtomic ? 0.f : bias[co1];
        #pragma unroll
        for (int na = 0; na < 8; na++){
            int n = wn * 64 + na * 8 + (lane & 3) * 2;
            int r = h0 + (n >> lgW);
            int w = n & (W - 1);
            size_t i0 = ((size_t)(b * 256 + co0) * H + r) * W + w;
            size_t i1 = ((size_t)(b * 256 + co1) * H + r) * W + w;
            if (useAtomic){
                atomicAdd(&out[i0],     acc[ma][na][0]);
                atomicAdd(&out[i0 + 1], acc[ma][na][1]);
                atomicAdd(&out[i1],     acc[ma][na][2]);
                atomicAdd(&out[i1 + 1], acc[ma][na][3]);
            } else {
                float2 v0; v0.x = acc[ma][na][0] + bv0; v0.y = acc[ma][na][1] + bv0;
                float2 v1; v1.x = acc[ma][na][2] + bv1; v1.y = acc[ma][na][3] + bv1;
                *reinterpret_cast<float2*>(&out[i0]) = v0;
                *reinterpret_cast<float2*>(&out[i1]) = v1;
            }
        }
    }
}

// ---------------- host orchestration ----------------
extern "C" void kernel_launch(void* const* d_in, const int* in_sizes, int n_in,
                              void* d_out, int out_size)
{
    const float *x[4]={0,0,0,0}, *rx[4]={0,0,0,0};
    const float *wm[4]={0,0,0,0}, *bm[4]={0,0,0,0}, *wo[4]={0,0,0,0}, *bo[4]={0,0,0,0};
    int wmi = 0, woi = 0, bi = 0;
    for (int i = 0; i < n_in; i++){
        int s = in_sizes[i];
        int lvl = -1;
        if      (s == 2*256*128*128) lvl = 0;
        else if (s == 2*256*64*64)   lvl = 1;
        else if (s == 2*256*32*32)   lvl = 2;
        else if (s == 2*256*16*16)   lvl = 3;
        if (lvl >= 0){
            if (!x[lvl]) x[lvl] = (const float*)d_in[i];
            else         rx[lvl] = (const float*)d_in[i];
        }
        else if (s == 1845504) wm[wmi++] = (const float*)d_in[i];
        else if (s ==  589824) wo[woi++] = (const float*)d_in[i];
        else if (s ==     256){
            if ((bi & 1) == 0) bm[bi >> 1] = (const float*)d_in[i];
            else               bo[bi >> 1] = (const float*)d_in[i];
            bi++;
        }
    }

    float *corrB, *mapB;
    __half *wmh, *woh, *amh, *aml, *aoh, *aol;
    cudaGetSymbolAddress((void**)&corrB, g_corr);
    cudaGetSymbolAddress((void**)&mapB,  g_map);
    cudaGetSymbolAddress((void**)&wmh, g_wm_h);
    cudaGetSymbolAddress((void**)&woh, g_wo_h);
    cudaGetSymbolAddress((void**)&amh, g_am_h); cudaGetSymbolAddress((void**)&aml, g_am_l);
    cudaGetSymbolAddress((void**)&aoh, g_ao_h); cudaGetSymbolAddress((void**)&aol, g_ao_l);

    cudaFuncSetAttribute(k_gemm, cudaFuncAttributeMaxDynamicSharedMemorySize, 165888);

    const int  Hl[4]      = {128, 64, 32, 16};
    const int  lgWl[4]    = {7, 6, 5, 4};
    const int  HWl[4]     = {16384, 4096, 1024, 256};
    const long corrOff[4] = {0, 9469952, 11837440, 12429312};
    const long mapOff[4]  = {0, 8388608, 10485760, 11010048};
    const long amOff[4]   = {0, 28121600, 35369984, 37293568};
    const long aoOff[4]   = {0, 8652800, 10883072, 11474944};
    const long wmOff[4]   = {0, 1916928, 3833856, 5750784};
    const long woOff[4]   = {0, 589824, 1179648, 1769472};
    const int  zmap[4]    = {1, 3, 9, 9};
    const int  zout[4]    = {1, 3, 9, 9};
    float* outp = (float*)d_out;

    // 1. pack weights (chunk-major + swizzle, fp16 hi)
    for (int l = 0; l < 4; l++){
        k_pack_w<<<(256*832 + 255)/256, 256>>>(wm[l], wmh + wmOff[l], 801, 832);
        k_pack_w<<<(256*256 + 255)/256, 256>>>(wo[l], woh + woOff[l], 256, 256);
    }

    // 2. correlation volumes
    for (int l = 0; l < 4; l++){
        int W = Hl[l];
        int groups = (W >= 32) ? 8 : 4;
        dim3 g(W / (groups * 4), Hl[l], 2);
        k_corr<<<g, groups * 17>>>(x[l], rx[l], corrB + corrOff[l], Hl[l], W, groups);
    }

    // 3. pack map activations (fp16 hi/lo)
    for (int l = 0; l < 4; l++){
        int H = Hl[l];
        int Np = 2 * (H + 2) * (H + 2);
        dim3 g((Np + 31) / 32, 832 / 32);
        k_pack_acts<<<g, dim3(32, 8)>>>(x[l], 256, rx[l], 256, corrB + corrOff[l], 289,
                                        amh + amOff[l], aml + amOff[l], H, H, 832);
    }

    // 4. map GEMMs (801 -> 256)
    for (int l = 0; l < 4; l++){
        int H = Hl[l];
        float* mout = mapB + mapOff[l];
        int total = 2 * 256 * HWl[l];
        int z = zmap[l];
        if (z > 1)
            k_init_bias<<<(total + 255)/256, 256>>>(mout, bm[l], HWl[l], total);
        dim3 g(2 * HWl[l] / 256, 2, z);
        k_gemm<<<g, 256, 165888>>>(wmh + wmOff[l],
                                   amh + amOff[l], aml + amOff[l],
                                   H, H, lgWl[l], 26, 9 / z, mout, bm[l], z > 1 ? 1 : 0);
    }

    // 5. top-down upsample add
    for (int l = 3; l >= 1; l--){
        int total = 2 * 256 * HWl[l - 1];
        k_up_add<<<(total + 255)/256, 256>>>(mapB + mapOff[l - 1], mapB + mapOff[l],
                                             Hl[l - 1], Hl[l - 1], total);
    }

    // 6. pack out activations
    for (int l = 0; l < 4; l++){
        int H = Hl[l];
        int Np = 2 * (H + 2) * (H + 2);
        dim3 g((Np + 31) / 32, 256 / 32);
        k_pack_acts<<<g, dim3(32, 8)>>>(mapB + mapOff[l], 256,
                                        (const float*)0, 0, (const float*)0, 0,
                                        aoh + aoOff[l], aol + aoOff[l], H, H, 256);
    }

    // 7. out GEMMs (256 -> 256) -> d_out
    for (int l = 0; l < 4; l++){
        int H = Hl[l];
        float* oo = outp + mapOff[l];
        int total = 2 * 256 * HWl[l];
        int z = zout[l];
        if (z > 1)
            k_init_bias<<<(total + 255)/256, 256>>>(oo, bo[l], HWl[l], total);
        dim3 g(2 * HWl[l] / 256, 2, z);
        k_gemm<<<g, 256, 165888>>>(woh + woOff[l],
                                   aoh + aoOff[l], aol + aoOff[l],
                                   H, H, lgWl[l], 8, 9 / z, oo, bo[l], z > 1 ? 1 : 0);
    }
}

// round 7
// speedup vs baseline: 2.6048x; 1.1276x over previous
#include <cuda_runtime.h>
#include <cuda_fp16.h>
#include <cstdint>
#include <cstddef>

#define PADC 8

// ---------------- static device buffers ----------------
__device__ __align__(256) float g_corr[12577280];
__device__ __align__(256) float g_map [11141120];
__device__ __align__(256) __half g_wm_h[7667712];   // [lvl][chunk26][tap9][co256][ci32] swizzled
__device__ __align__(256) __half g_wo_h[2359296];   // [lvl][chunk8][tap9][co256][ci32]
__device__ __align__(256) __half g_am_h[37832704];  // [lvl][chunk][b][Hp][Wp][32] swizzled
__device__ __align__(256) __half g_am_l[37832704];
__device__ __align__(256) __half g_ao_h[11640832];
__device__ __align__(256) __half g_ao_l[11640832];

// ---------------- PTX helpers (compute_103 baseline-safe) ----------------
__device__ __forceinline__ uint32_t smem_u32(const void* p){
    uint32_t a;
    asm("{ .reg .u64 t; cvta.to.shared.u64 t, %1; cvt.u32.u64 %0, t; }" : "=r"(a) : "l"(p));
    return a;
}
__device__ __forceinline__ void mbar_init(uint32_t a, uint32_t cnt){
    asm volatile("mbarrier.init.shared.b64 [%0], %1;" :: "r"(a), "r"(cnt) : "memory");
}
__device__ __forceinline__ void mbar_expect(uint32_t a, uint32_t bytes){
    asm volatile("mbarrier.arrive.expect_tx.shared.b64 _, [%0], %1;" :: "r"(a), "r"(bytes) : "memory");
}
__device__ __forceinline__ void mbar_wait(uint32_t a, int parity){
    asm volatile(
        "{\n\t.reg .pred P;\n\t"
        "WL_%=:\n\t"
        "mbarrier.try_wait.parity.acquire.cta.shared::cta.b64 P, [%0], %1, 0x989680;\n\t"
        "@P bra WD_%=;\n\t"
        "bra WL_%=;\n\t"
        "WD_%=:\n\t}"
        :: "r"(a), "r"(parity) : "memory");
}
__device__ __forceinline__ void bulk_cp(uint32_t dst, const void* src, uint32_t bytes, uint32_t mbar){
    asm volatile(
        "cp.async.bulk.shared::cluster.global.mbarrier::complete_tx::bytes [%0], [%1], %2, [%3];"
        :: "r"(dst), "l"(src), "r"(bytes), "r"(mbar) : "memory");
}
__device__ __forceinline__ void ldmx4(uint32_t* r, uint32_t addr){
    asm volatile("ldmatrix.sync.aligned.m8n8.x4.shared.b16 {%0,%1,%2,%3}, [%4];"
                 : "=r"(r[0]), "=r"(r[1]), "=r"(r[2]), "=r"(r[3]) : "r"(addr));
}
__device__ __forceinline__ void mma16816(float* c, const uint32_t* a, uint32_t b0, uint32_t b1){
    asm volatile(
        "mma.sync.aligned.m16n8k16.row.col.f32.f16.f16.f32 "
        "{%0,%1,%2,%3}, {%4,%5,%6,%7}, {%8,%9}, {%0,%1,%2,%3};"
        : "+f"(c[0]), "+f"(c[1]), "+f"(c[2]), "+f"(c[3])
        : "r"(a[0]), "r"(a[1]), "r"(a[2]), "r"(a[3]), "r"(b0), "r"(b1));
}

// ---------------- correlation (unchanged, validated) ----------------
__global__ void k_corr(const float* __restrict__ x, const float* __restrict__ ref,
                       float* __restrict__ corr, int H, int W, int groups){
    int g  = threadIdx.x % groups;
    int dy = threadIdx.x / groups;
    if (dy >= 17) return;
    int w0 = blockIdx.x * groups * 4;
    int h  = blockIdx.y;
    int b  = blockIdx.z;
    int wbase = w0 + g * 4;

    float acc[17][4];
    #pragma unroll
    for (int j = 0; j < 17; j++){ acc[j][0]=0.f; acc[j][1]=0.f; acc[j][2]=0.f; acc[j][3]=0.f; }

    int r = h + dy - PADC;
    int HW = H * W;
    if (r >= 0 && r < H){
        const float* xb = x   + ((b * 256) * H + h) * W;
        const float* rb = ref + ((b * 256) * H + r) * W;
        int q0 = wbase - PADC;
        bool interior = (q0 >= 0) && (q0 + 20 <= W);
        for (int c = 0; c < 256; c++){
            const float4 xv = *reinterpret_cast<const float4*>(xb + c * HW + wbase);
            const float* rr = rb + c * HW;
            float rv[20];
            if (interior){
                #pragma unroll
                for (int t = 0; t < 5; t++){
                    float4 v = *reinterpret_cast<const float4*>(rr + q0 + t * 4);
                    rv[t*4+0]=v.x; rv[t*4+1]=v.y; rv[t*4+2]=v.z; rv[t*4+3]=v.w;
                }
            } else {
                #pragma unroll
                for (int t = 0; t < 20; t++){
                    int q = q0 + t;
                    rv[t] = (q >= 0 && q < W) ? rr[q] : 0.f;
                }
            }
            #pragma unroll
            for (int j = 0; j < 17; j++){
                acc[j][0] += xv.x * rv[j];
                acc[j][1] += xv.y * rv[j+1];
                acc[j][2] += xv.z * rv[j+2];
                acc[j][3] += xv.w * rv[j+3];
            }
        }
    }
    #pragma unroll
    for (int j = 0; j < 17; j++){
        int d = dy * 17 + j;
        float4 o; o.x=acc[j][0]; o.y=acc[j][1]; o.z=acc[j][2]; o.w=acc[j][3];
        *reinterpret_cast<float4*>(corr + ((b * 289 + d) * H + h) * W + wbase) = o;
    }
}

// ---------------- misc small kernels ----------------
__global__ void k_init_bias(float* __restrict__ out, const float* __restrict__ bias,
                            int HW, int total){
    int i = blockIdx.x * blockDim.x + threadIdx.x;
    if (i < total) out[i] = bias[(i / HW) & 255];
}
__global__ void k_up_add(float* __restrict__ dst, const float* __restrict__ src,
                         int H, int W, int total){
    int i = blockIdx.x * blockDim.x + threadIdx.x;
    if (i >= total) return;
    int w = i % W; int t = i / W; int h = t % H; int bc = t / H;
    dst[i] += src[(bc * (H >> 1) + (h >> 1)) * (W >> 1) + (w >> 1)];
}

// ---------------- weight pack: w[co][ci][3][3] -> [chunk][tap][co][32ci] swizzled ----------------
__global__ void k_pack_w(const float* __restrict__ w, __half* __restrict__ oh,
                         int Cin, int Cpad){
    int i = blockIdx.x * 256 + threadIdx.x;
    if (i >= 256 * Cpad) return;
    int co = i / Cpad, ci = i % Cpad;
    int c = ci >> 5, cl = ci & 31;
    int gsw = (cl >> 3) ^ ((co >> 1) & 3);
    #pragma unroll
    for (int t = 0; t < 9; t++){
        float v = (ci < Cin) ? w[(size_t)(co * Cin + ci) * 9 + t] : 0.f;
        size_t o = (((size_t)c * 9 + t) * 256 + co) * 32 + (gsw << 3) + (cl & 7);
        oh[o] = __float2half_rn(v);
    }
}

// ---------------- act pack: NCHW fp32 -> [chunk][b][Hp][Wp][32] fp16 hi/lo, swizzled ----------------
__global__ void k_pack_acts(const float* __restrict__ S0, int C0,
                            const float* __restrict__ S1, int C1,
                            const float* __restrict__ S2, int C2,
                            __half* __restrict__ Ph, __half* __restrict__ Pl,
                            int H, int W, int Cpad){
    __shared__ float t[32][33];
    int Hp = H + 2, Wp = W + 2, HW = H * W, Np = 2 * Hp * Wp;
    int p0 = blockIdx.x * 32, c0 = blockIdx.y * 32;
    int px = p0 + threadIdx.x;
    int b = 0, pix = 0; bool inter = false;
    if (px < Np){
        b = px / (Hp * Wp); int r = px % (Hp * Wp); int hp = r / Wp, wp = r % Wp;
        if (hp >= 1 && hp <= H && wp >= 1 && wp <= W){ inter = true; pix = (hp - 1) * W + (wp - 1); }
    }
    #pragma unroll
    for (int dyy = 0; dyy < 32; dyy += 8){
        int ci = c0 + (int)threadIdx.y + dyy;
        float v = 0.f;
        if (inter){
            if (ci < C0)                 v = S0[(size_t)(b * C0 + ci) * HW + pix];
            else if (ci < C0 + C1)       v = S1[(size_t)(b * C1 + ci - C0) * HW + pix];
            else if (ci < C0 + C1 + C2)  v = S2[(size_t)(b * C2 + (ci - C0 - C1)) * HW + pix];
        }
        t[threadIdx.y + dyy][threadIdx.x] = v;
    }
    __syncthreads();
    int ft = threadIdx.y * 32 + threadIdx.x;
    int pl = ft >> 3, sub = ft & 7;
    int px2 = p0 + pl;
    if (px2 < Np){
        size_t chStride = (size_t)2 * Hp * Wp * 32;
        int gsw = (sub >> 1) ^ ((px2 >> 1) & 3);
        size_t base = (size_t)(c0 >> 5) * chStride + (size_t)px2 * 32 + (gsw << 3) + (sub & 1) * 4;
        float v0 = t[sub*4+0][pl], v1 = t[sub*4+1][pl], v2 = t[sub*4+2][pl], v3 = t[sub*4+3][pl];
        __half h0 = __float2half_rn(v0), h1 = __float2half_rn(v1);
        __half h2 = __float2half_rn(v2), h3 = __float2half_rn(v3);
        uint32_t uh0 = (uint32_t)__half_as_ushort(h0) | ((uint32_t)__half_as_ushort(h1) << 16);
        uint32_t uh1 = (uint32_t)__half_as_ushort(h2) | ((uint32_t)__half_as_ushort(h3) << 16);
        uint2 wh; wh.x = uh0; wh.y = uh1;
        *reinterpret_cast<uint2*>(Ph + base) = wh;
        __half l0 = __float2half_rn(v0 - __half2float(h0));
        __half l1 = __float2half_rn(v1 - __half2float(h1));
        __half l2 = __float2half_rn(v2 - __half2float(h2));
        __half l3 = __float2half_rn(v3 - __half2float(h3));
        uint32_t ul0 = (uint32_t)__half_as_ushort(l0) | ((uint32_t)__half_as_ushort(l1) << 16);
        uint32_t ul1 = (uint32_t)__half_as_ushort(l2) | ((uint32_t)__half_as_ushort(l3) << 16);
        uint2 wl; wl.x = ul0; wl.y = ul1;
        *reinterpret_cast<uint2*>(Pl + base) = wl;
    }
}

// ---------------- merged multi-level fp16 2-pass implicit-conv GEMM ----------------
struct GemmParams {
    const __half* A;            // weight base
    const __half* BhB;          // act hi base
    const __half* BlB;          // act lo base
    float*        out[4];
    const float*  bias[4];
    long aOff[4];
    long bOff[4];
    int  H[4];
    int  lgW[4];
    int  zc[4];                 // z-split count per level
    int  tpz[4];                // taps per z-slice
    int  blkBase[5];            // block-id ranges per level
    int  CH;                    // ci chunks (26 map / 8 out)
};

__global__ __launch_bounds__(256)
void k_gemm(const __grid_constant__ GemmParams P)
{
    extern __shared__ char dsm[];
    __shared__ __align__(8) unsigned long long mb[6];

    // ---- decode level / tile ----
    const int bid = blockIdx.x;
    int l = 0;
    if (bid >= P.blkBase[1]) l = 1;
    if (bid >= P.blkBase[2]) l = 2;
    if (bid >= P.blkBase[3]) l = 3;
    const int rel = bid - P.blkBase[l];
    const int zc = P.zc[l], tapsPerZ = P.tpz[l];
    const int zi = rel % zc;
    const int tt = rel / zc;
    const int m0 = (tt & 1) * 128;
    const int nt = tt >> 1;
    const int H = P.H[l], W = H, lgW = P.lgW[l];
    const __half* A  = P.A   + P.aOff[l];
    const __half* Bh = P.BhB + P.bOff[l];
    const __half* Bl = P.BlB + P.bOff[l];
    float* out = P.out[l];
    const float* bias = P.bias[l];
    const int useAtomic = (zc > 1);
    const int tapBeg = zi * tapsPerZ;
    const int CH = P.CH;

    const uint32_t smemBase = smem_u32(dsm);
    uint32_t A_OFF[4], B_OFF[2];
    #pragma unroll
    for (int s = 0; s < 4; s++) A_OFF[s] = smemBase + s * 8192u;
    B_OFF[0] = smemBase + 32768u;
    B_OFF[1] = smemBase + 32768u + 66560u;
    const uint32_t MBA = smem_u32(&mb[0]);
    const uint32_t MBB = smem_u32(&mb[4]);

    const int tid = threadIdx.x, wid = tid >> 5, lane = tid & 31;
    const int R = 256 >> lgW;
    const int Hp = H + 2, Wp = W + 2;
    const int tilesPerB = H / R;
    const int b  = nt / tilesPerB;
    const int h0 = (nt % tilesPerB) * R;
    const int q0 = (b * Hp + h0) * Wp;
    const uint32_t Bbytes = (uint32_t)(R + 2) * Wp * 64u;
    const size_t chStride = (size_t)2 * Hp * Wp * 32;

    if (tid == 0){
        #pragma unroll
        for (int i = 0; i < 6; i++) mbar_init(MBA + i * 8, 1);
    }
    __syncthreads();

    const int nA = CH * tapsPerZ;

    auto issueA = [&](int ia){
        int c = ia / tapsPerZ, tap = ia % tapsPerZ;
        const __half* src = A + ((((size_t)c * 9 + (tapBeg + tap)) * 256 + m0) << 5);
        int s = ia & 3;
        mbar_expect(MBA + s * 8, 8192u);
        bulk_cp(A_OFF[s], src, 8192u, MBA + s * 8);
    };
    auto issueB = [&](int c){
        int s = c & 1;
        mbar_expect(MBB + s * 8, 2u * Bbytes);
        bulk_cp(B_OFF[s],          Bh + (size_t)c * chStride + ((size_t)q0 << 5), Bbytes, MBB + s * 8);
        bulk_cp(B_OFF[s] + 33280u, Bl + (size_t)c * chStride + ((size_t)q0 << 5), Bbytes, MBB + s * 8);
    };

    const int lr  = lane & 7;
    const int lm8 = ((lane >> 3) & 1) * 8;
    const int lk  = lane >> 4;
    const int wm  = wid & 1;
    const int wn  = wid >> 1;
    const int rowA = wm * 64 + lm8 + lr;
    const int xorA = (lr >> 1) & 3;
    int rB[4], wB[4];
    #pragma unroll
    for (int g = 0; g < 4; g++){
        int n = wn * 64 + g * 16 + lm8 + lr;
        rB[g] = n >> lgW;
        wB[g] = n & (W - 1);
    }

    float acc[4][8][4];
    #pragma unroll
    for (int i = 0; i < 4; i++)
        #pragma unroll
        for (int j = 0; j < 8; j++)
            #pragma unroll
            for (int k = 0; k < 4; k++) acc[i][j][k] = 0.f;

    if (tid == 0){
        issueB(0);
        issueA(0);
        if (nA > 1) issueA(1);
        if (nA > 2) issueA(2);
    }

    for (int it = 0; it < nA; ++it){
        int c = it / tapsPerZ, tap = it % tapsPerZ;
        if (tid == 0){
            if (it + 3 < nA) issueA(it + 3);
            if (tap == 0 && c + 1 < CH) issueB(c + 1);
        }
        mbar_wait(MBA + (it & 3) * 8, (it >> 2) & 1);
        if (tap == 0) mbar_wait(MBB + (c & 1) * 8, (c >> 1) & 1);

        const uint32_t Ab = A_OFF[it & 3];
        const uint32_t Bb = B_OFF[c & 1];
        const int tIdx = tapBeg + tap;
        const int dy = tIdx / 3, dx = tIdx - dy * 3;

        uint32_t sAdr[4]; int xorB[4];
        #pragma unroll
        for (int g = 0; g < 4; g++){
            int s = (rB[g] + dy) * Wp + wB[g] + dx;
            sAdr[g] = Bb + (uint32_t)s * 64u;
            xorB[g] = ((q0 + s) >> 1) & 3;
        }

        #pragma unroll
        for (int ks = 0; ks < 2; ks++){
            const int gA = (2 * ks + lk) ^ xorA;
            uint32_t a[4][4];
            #pragma unroll
            for (int ma = 0; ma < 4; ma++)
                ldmx4(a[ma], Ab + (uint32_t)(rowA + ma * 16) * 64u + ((uint32_t)gA << 4));
            #pragma unroll
            for (int pass = 0; pass < 2; pass++){
                uint32_t bb[4][4];
                #pragma unroll
                for (int g = 0; g < 4; g++){
                    int gB = (2 * ks + lk) ^ xorB[g];
                    ldmx4(bb[g], sAdr[g] + (uint32_t)pass * 33280u + ((uint32_t)gB << 4));
                }
                #pragma unroll
                for (int ma = 0; ma < 4; ma++)
                    #pragma unroll
                    for (int na = 0; na < 8; na++)
                        mma16816(acc[ma][na], a[ma], bb[na >> 1][na & 1], bb[na >> 1][2 + (na & 1)]);
            }
        }
        __syncthreads();
    }

    // epilogue: NCHW
    #pragma unroll
    for (int ma = 0; ma < 4; ma++){
        int co0 = m0 + wm * 64 + ma * 16 + (lane >> 2);
        int co1 = co0 + 8;
        float bv0 = useAtomic ? 0.f : bias[co0];
        float bv1 = useAtomic ? 0.f : bias[co1];
        #pragma unroll
        for (int na = 0; na < 8; na++){
            int n = wn * 64 + na * 8 + (lane & 3) * 2;
            int r = h0 + (n >> lgW);
            int w = n & (W - 1);
            size_t i0 = ((size_t)(b * 256 + co0) * H + r) * W + w;
            size_t i1 = ((size_t)(b * 256 + co1) * H + r) * W + w;
            if (useAtomic){
                atomicAdd(&out[i0],     acc[ma][na][0]);
                atomicAdd(&out[i0 + 1], acc[ma][na][1]);
                atomicAdd(&out[i1],     acc[ma][na][2]);
                atomicAdd(&out[i1 + 1], acc[ma][na][3]);
            } else {
                float2 v0; v0.x = acc[ma][na][0] + bv0; v0.y = acc[ma][na][1] + bv0;
                float2 v1; v1.x = acc[ma][na][2] + bv1; v1.y = acc[ma][na][3] + bv1;
                *reinterpret_cast<float2*>(&out[i0]) = v0;
                *reinterpret_cast<float2*>(&out[i1]) = v1;
            }
        }
    }
}

// ---------------- host orchestration ----------------
extern "C" void kernel_launch(void* const* d_in, const int* in_sizes, int n_in,
                              void* d_out, int out_size)
{
    const float *x[4]={0,0,0,0}, *rx[4]={0,0,0,0};
    const float *wm[4]={0,0,0,0}, *bm[4]={0,0,0,0}, *wo[4]={0,0,0,0}, *bo[4]={0,0,0,0};
    int wmi = 0, woi = 0, bi = 0;
    for (int i = 0; i < n_in; i++){
        int s = in_sizes[i];
        int lvl = -1;
        if      (s == 2*256*128*128) lvl = 0;
        else if (s == 2*256*64*64)   lvl = 1;
        else if (s == 2*256*32*32)   lvl = 2;
        else if (s == 2*256*16*16)   lvl = 3;
        if (lvl >= 0){
            if (!x[lvl]) x[lvl] = (const float*)d_in[i];
            else         rx[lvl] = (const float*)d_in[i];
        }
        else if (s == 1845504) wm[wmi++] = (const float*)d_in[i];
        else if (s ==  589824) wo[woi++] = (const float*)d_in[i];
        else if (s ==     256){
            if ((bi & 1) == 0) bm[bi >> 1] = (const float*)d_in[i];
            else               bo[bi >> 1] = (const float*)d_in[i];
            bi++;
        }
    }

    float *corrB, *mapB;
    __half *wmh, *woh, *amh, *aml, *aoh, *aol;
    cudaGetSymbolAddress((void**)&corrB, g_corr);
    cudaGetSymbolAddress((void**)&mapB,  g_map);
    cudaGetSymbolAddress((void**)&wmh, g_wm_h);
    cudaGetSymbolAddress((void**)&woh, g_wo_h);
    cudaGetSymbolAddress((void**)&amh, g_am_h); cudaGetSymbolAddress((void**)&aml, g_am_l);
    cudaGetSymbolAddress((void**)&aoh, g_ao_h); cudaGetSymbolAddress((void**)&aol, g_ao_l);

    cudaFuncSetAttribute(k_gemm, cudaFuncAttributeMaxDynamicSharedMemorySize, 165888);

    const int  Hl[4]      = {128, 64, 32, 16};
    const int  lgWl[4]    = {7, 6, 5, 4};
    const int  HWl[4]     = {16384, 4096, 1024, 256};
    const long corrOff[4] = {0, 9469952, 11837440, 12429312};
    const long mapOff[4]  = {0, 8388608, 10485760, 11010048};
    const long amOff[4]   = {0, 28121600, 35369984, 37293568};
    const long aoOff[4]   = {0, 8652800, 10883072, 11474944};
    const long wmOff[4]   = {0, 1916928, 3833856, 5750784};
    const long woOff[4]   = {0, 589824, 1179648, 1769472};
    const int  zl[4]      = {1, 3, 9, 9};
    const int  tpzl[4]    = {9, 3, 1, 1};
    float* outp = (float*)d_out;

    // tile counts per level: (2*HW/256) n-tiles * 2 m-tiles * z
    int blkBase[5]; blkBase[0] = 0;
    for (int l = 0; l < 4; l++)
        blkBase[l + 1] = blkBase[l] + (2 * HWl[l] / 256) * 2 * zl[l];
    // = {0, 256, 448, 592, 628}

    // 1. pack weights
    for (int l = 0; l < 4; l++){
        k_pack_w<<<(256*832 + 255)/256, 256>>>(wm[l], wmh + wmOff[l], 801, 832);
        k_pack_w<<<(256*256 + 255)/256, 256>>>(wo[l], woh + woOff[l], 256, 256);
    }

    // 2. correlation volumes
    for (int l = 0; l < 4; l++){
        int W = Hl[l];
        int groups = (W >= 32) ? 8 : 4;
        dim3 g(W / (groups * 4), Hl[l], 2);
        k_corr<<<g, groups * 17>>>(x[l], rx[l], corrB + corrOff[l], Hl[l], W, groups);
    }

    // 3. pack map activations
    for (int l = 0; l < 4; l++){
        int H = Hl[l];
        int Np = 2 * (H + 2) * (H + 2);
        dim3 g((Np + 31) / 32, 832 / 32);
        k_pack_acts<<<g, dim3(32, 8)>>>(x[l], 256, rx[l], 256, corrB + corrOff[l], 289,
                                        amh + amOff[l], aml + amOff[l], H, H, 832);
    }

    // 4. init bias for atomic levels (map), then ONE merged map GEMM launch
    for (int l = 1; l < 4; l++){
        int total = 2 * 256 * HWl[l];
        k_init_bias<<<(total + 255)/256, 256>>>(mapB + mapOff[l], bm[l], HWl[l], total);
    }
    {
        GemmParams P;
        P.A = wmh; P.BhB = amh; P.BlB = aml;
        for (int l = 0; l < 4; l++){
            P.out[l] = mapB + mapOff[l]; P.bias[l] = bm[l];
            P.aOff[l] = wmOff[l]; P.bOff[l] = amOff[l];
            P.H[l] = Hl[l]; P.lgW[l] = lgWl[l]; P.zc[l] = zl[l]; P.tpz[l] = tpzl[l];
        }
        for (int i = 0; i < 5; i++) P.blkBase[i] = blkBase[i];
        P.CH = 26;
        k_gemm<<<blkBase[4], 256, 165888>>>(P);
    }

    // 5. top-down upsample add
    for (int l = 3; l >= 1; l--){
        int total = 2 * 256 * HWl[l - 1];
        k_up_add<<<(total + 255)/256, 256>>>(mapB + mapOff[l - 1], mapB + mapOff[l],
                                             Hl[l - 1], Hl[l - 1], total);
    }

    // 6. pack out activations
    for (int l = 0; l < 4; l++){
        int H = Hl[l];
        int Np = 2 * (H + 2) * (H + 2);
        dim3 g((Np + 31) / 32, 256 / 32);
        k_pack_acts<<<g, dim3(32, 8)>>>(mapB + mapOff[l], 256,
                                        (const float*)0, 0, (const float*)0, 0,
                                        aoh + aoOff[l], aol + aoOff[l], H, H, 256);
    }

    // 7. init bias for atomic levels (out), then ONE merged out GEMM launch
    for (int l = 1; l < 4; l++){
        int total = 2 * 256 * HWl[l];
        k_init_bias<<<(total + 255)/256, 256>>>(outp + mapOff[l], bo[l], HWl[l], total);
    }
    {
        GemmParams P;
        P.A = woh; P.BhB = aoh; P.BlB = aol;
        for (int l = 0; l < 4; l++){
            P.out[l] = outp + mapOff[l]; P.bias[l] = bo[l];
            P.aOff[l] = woOff[l]; P.bOff[l] = aoOff[l];
            P.H[l] = Hl[l]; P.lgW[l] = lgWl[l]; P.zc[l] = zl[l]; P.tpz[l] = tpzl[l];
        }
        for (int i = 0; i < 5; i++) P.blkBase[i] = blkBase[i];
        P.CH = 8;
        k_gemm<<<blkBase[4], 256, 165888>>>(P);
    }
}

// round 8
// speedup vs baseline: 2.9859x; 1.1463x over previous
#include <cuda_runtime.h>
#include <cuda_fp16.h>
#include <cstdint>
#include <cstddef>

#define PADC 8

// ---------------- static device buffers ----------------
__device__ __align__(256) float g_corr[12577280];
__device__ __align__(256) float g_map [11141120];
__device__ __align__(256) __half g_wm_h[7667712];   // [lvl][chunk26][tap9][co256][ci32] swizzled
__device__ __align__(256) __half g_wo_h[2359296];   // [lvl][chunk8][tap9][co256][ci32]
__device__ __align__(256) __half g_am_h[37832704];  // [lvl][chunk][b][Hp][Wp][32] swizzled
__device__ __align__(256) __half g_am_l[37832704];
__device__ __align__(256) __half g_ao_h[11640832];
__device__ __align__(256) __half g_ao_l[11640832];

// ---------------- PTX helpers (compute_103 baseline-safe) ----------------
__device__ __forceinline__ uint32_t smem_u32(const void* p){
    uint32_t a;
    asm("{ .reg .u64 t; cvta.to.shared.u64 t, %1; cvt.u32.u64 %0, t; }" : "=r"(a) : "l"(p));
    return a;
}
__device__ __forceinline__ void mbar_init(uint32_t a, uint32_t cnt){
    asm volatile("mbarrier.init.shared.b64 [%0], %1;" :: "r"(a), "r"(cnt) : "memory");
}
__device__ __forceinline__ void mbar_expect(uint32_t a, uint32_t bytes){
    asm volatile("mbarrier.arrive.expect_tx.shared.b64 _, [%0], %1;" :: "r"(a), "r"(bytes) : "memory");
}
__device__ __forceinline__ void mbar_wait(uint32_t a, int parity){
    asm volatile(
        "{\n\t.reg .pred P;\n\t"
        "WL_%=:\n\t"
        "mbarrier.try_wait.parity.acquire.cta.shared::cta.b64 P, [%0], %1, 0x989680;\n\t"
        "@P bra WD_%=;\n\t"
        "bra WL_%=;\n\t"
        "WD_%=:\n\t}"
        :: "r"(a), "r"(parity) : "memory");
}
__device__ __forceinline__ void bulk_cp(uint32_t dst, const void* src, uint32_t bytes, uint32_t mbar){
    asm volatile(
        "cp.async.bulk.shared::cluster.global.mbarrier::complete_tx::bytes [%0], [%1], %2, [%3];"
        :: "r"(dst), "l"(src), "r"(bytes), "r"(mbar) : "memory");
}
__device__ __forceinline__ void ldmx4(uint32_t* r, uint32_t addr){
    asm volatile("ldmatrix.sync.aligned.m8n8.x4.shared.b16 {%0,%1,%2,%3}, [%4];"
                 : "=r"(r[0]), "=r"(r[1]), "=r"(r[2]), "=r"(r[3]) : "r"(addr));
}
__device__ __forceinline__ void mma16816(float* c, const uint32_t* a, uint32_t b0, uint32_t b1){
    asm volatile(
        "mma.sync.aligned.m16n8k16.row.col.f32.f16.f16.f32 "
        "{%0,%1,%2,%3}, {%4,%5,%6,%7}, {%8,%9}, {%0,%1,%2,%3};"
        : "+f"(c[0]), "+f"(c[1]), "+f"(c[2]), "+f"(c[3])
        : "r"(a[0]), "r"(a[1]), "r"(a[2]), "r"(a[3]), "r"(b0), "r"(b1));
}

// ================= merged init bias (3 regions) =================
struct InitParams {
    float* out[3];
    const float* bias[3];
    int HW[3];
    long base[4];
};
__global__ void k_init_all(const __grid_constant__ InitParams P){
    long i = (long)blockIdx.x * blockDim.x + threadIdx.x;
    if (i >= P.base[3]) return;
    int r = 0;
    if (i >= P.base[1]) r = 1;
    if (i >= P.base[2]) r = 2;
    long loc = i - P.base[r];
    P.out[r][loc] = P.bias[r][(loc / P.HW[r]) & 255];
}

// ================= merged weight pack (8 tensors) =================
struct PackWParams {
    const float* src[8];
    __half* dst[8];
    int Cin[8];
    int Cpad[8];
    long base[9];
};
__global__ void k_pack_w_all(const __grid_constant__ PackWParams P){
    long i = (long)blockIdx.x * 256 + threadIdx.x;
    if (i >= P.base[8]) return;
    int t = 0;
    #pragma unroll
    for (int k = 1; k < 8; k++) if (i >= P.base[k]) t = k;
    long loc = i - P.base[t];
    int Cpad = P.Cpad[t], Cin = P.Cin[t];
    int co = (int)(loc / Cpad), ci = (int)(loc % Cpad);
    int c = ci >> 5, cl = ci & 31;
    int gsw = (cl >> 3) ^ ((co >> 1) & 3);
    const float* w = P.src[t];
    __half* oh = P.dst[t];
    #pragma unroll
    for (int tap = 0; tap < 9; tap++){
        float v = (ci < Cin) ? w[(size_t)(co * Cin + ci) * 9 + tap] : 0.f;
        size_t o = (((size_t)c * 9 + tap) * 256 + co) * 32 + (gsw << 3) + (cl & 7);
        oh[o] = __float2half_rn(v);
    }
}

// ================= merged correlation (4 levels) =================
struct CorrParams {
    const float* x[4];
    const float* rx[4];
    float* out[4];
    int H[4];
    int GX[4];
    int grp[4];
    int blkBase[5];
};
__global__ void k_corr_all(const __grid_constant__ CorrParams P){
    const int bid = blockIdx.x;
    int l = 0;
    if (bid >= P.blkBase[1]) l = 1;
    if (bid >= P.blkBase[2]) l = 2;
    if (bid >= P.blkBase[3]) l = 3;
    const int rel = bid - P.blkBase[l];
    const int H = P.H[l], W = H;
    const int GX = P.GX[l], groups = P.grp[l];
    const int gx = rel % GX;
    const int t2 = rel / GX;
    const int h = t2 % H;
    const int b = t2 / H;

    int g  = threadIdx.x % groups;
    int dy = threadIdx.x / groups;
    if (dy >= 17) return;
    int wbase = gx * groups * 4 + g * 4;

    const float* x   = P.x[l];
    const float* ref = P.rx[l];
    float* corr      = P.out[l];

    float acc[17][4];
    #pragma unroll
    for (int j = 0; j < 17; j++){ acc[j][0]=0.f; acc[j][1]=0.f; acc[j][2]=0.f; acc[j][3]=0.f; }

    int r = h + dy - PADC;
    int HW = H * W;
    if (r >= 0 && r < H){
        const float* xb = x   + ((b * 256) * H + h) * W;
        const float* rb = ref + ((b * 256) * H + r) * W;
        int q0 = wbase - PADC;
        bool interior = (q0 >= 0) && (q0 + 20 <= W);
        for (int c = 0; c < 256; c++){
            const float4 xv = *reinterpret_cast<const float4*>(xb + c * HW + wbase);
            const float* rr = rb + c * HW;
            float rv[20];
            if (interior){
                #pragma unroll
                for (int t = 0; t < 5; t++){
                    float4 v = *reinterpret_cast<const float4*>(rr + q0 + t * 4);
                    rv[t*4+0]=v.x; rv[t*4+1]=v.y; rv[t*4+2]=v.z; rv[t*4+3]=v.w;
                }
            } else {
                #pragma unroll
                for (int t = 0; t < 20; t++){
                    int q = q0 + t;
                    rv[t] = (q >= 0 && q < W) ? rr[q] : 0.f;
                }
            }
            #pragma unroll
            for (int j = 0; j < 17; j++){
                acc[j][0] += xv.x * rv[j];
                acc[j][1] += xv.y * rv[j+1];
                acc[j][2] += xv.z * rv[j+2];
                acc[j][3] += xv.w * rv[j+3];
            }
        }
    }
    #pragma unroll
    for (int j = 0; j < 17; j++){
        int d = dy * 17 + j;
        float4 o; o.x=acc[j][0]; o.y=acc[j][1]; o.z=acc[j][2]; o.w=acc[j][3];
        *reinterpret_cast<float4*>(corr + ((b * 289 + d) * H + h) * W + wbase) = o;
    }
}

// ================= merged map-act pack (4 levels, Cpad=832) =================
struct PackMapParams {
    const float* x[4];
    const float* rx[4];
    const float* corr[4];
    __half* Ph[4];
    __half* Pl[4];
    int H[4];
    int npb[4];
    int blkBase[5];
};
__global__ void k_pack_map_all(const __grid_constant__ PackMapParams P){
    __shared__ float t[32][33];
    const int bid = blockIdx.x;
    int l = 0;
    if (bid >= P.blkBase[1]) l = 1;
    if (bid >= P.blkBase[2]) l = 2;
    if (bid >= P.blkBase[3]) l = 3;
    const int rel = bid - P.blkBase[l];
    const int npb = P.npb[l];
    const int bxp = rel % npb;
    const int c0  = (rel / npb) * 32;
    const int H = P.H[l], W = H;
    const int Hp = H + 2, Wp = W + 2, HW = H * W, Np = 2 * Hp * Wp;
    const int p0 = bxp * 32;

    int px = p0 + threadIdx.x;
    int b = 0, pix = 0; bool inter = false;
    if (px < Np){
        b = px / (Hp * Wp); int r = px % (Hp * Wp); int hp = r / Wp, wp = r % Wp;
        if (hp >= 1 && hp <= H && wp >= 1 && wp <= W){ inter = true; pix = (hp - 1) * W + (wp - 1); }
    }
    const float* X  = P.x[l];
    const float* RX = P.rx[l];
    const float* CR = P.corr[l];
    #pragma unroll
    for (int dyy = 0; dyy < 32; dyy += 8){
        int ci = c0 + (int)threadIdx.y + dyy;
        float v = 0.f;
        if (inter){
            if (ci < 256)       v = X [(size_t)(b * 256 + ci) * HW + pix];
            else if (ci < 512)  v = RX[(size_t)(b * 256 + ci - 256) * HW + pix];
            else if (ci < 801)  v = CR[(size_t)(b * 289 + ci - 512) * HW + pix];
        }
        t[threadIdx.y + dyy][threadIdx.x] = v;
    }
    __syncthreads();
    int ft = threadIdx.y * 32 + threadIdx.x;
    int pl = ft >> 3, sub = ft & 7;
    int px2 = p0 + pl;
    if (px2 < Np){
        size_t chStride = (size_t)2 * Hp * Wp * 32;
        int gsw = (sub >> 1) ^ ((px2 >> 1) & 3);
        size_t base = (size_t)(c0 >> 5) * chStride + (size_t)px2 * 32 + (gsw << 3) + (sub & 1) * 4;
        float v0 = t[sub*4+0][pl], v1 = t[sub*4+1][pl], v2 = t[sub*4+2][pl], v3 = t[sub*4+3][pl];
        __half h0 = __float2half_rn(v0), h1 = __float2half_rn(v1);
        __half h2 = __float2half_rn(v2), h3 = __float2half_rn(v3);
        uint32_t uh0 = (uint32_t)__half_as_ushort(h0) | ((uint32_t)__half_as_ushort(h1) << 16);
        uint32_t uh1 = (uint32_t)__half_as_ushort(h2) | ((uint32_t)__half_as_ushort(h3) << 16);
        uint2 wh; wh.x = uh0; wh.y = uh1;
        *reinterpret_cast<uint2*>(P.Ph[l] + base) = wh;
        __half l0 = __float2half_rn(v0 - __half2float(h0));
        __half l1 = __float2half_rn(v1 - __half2float(h1));
        __half l2 = __float2half_rn(v2 - __half2float(h2));
        __half l3 = __float2half_rn(v3 - __half2float(h3));
        uint32_t ul0 = (uint32_t)__half_as_ushort(l0) | ((uint32_t)__half_as_ushort(l1) << 16);
        uint32_t ul1 = (uint32_t)__half_as_ushort(l2) | ((uint32_t)__half_as_ushort(l3) << 16);
        uint2 wl; wl.x = ul0; wl.y = ul1;
        *reinterpret_cast<uint2*>(P.Pl[l] + base) = wl;
    }
}

// ================= merged out-act pack with fused upsample cascade =================
// value(l,b,ci,h,w) = sum_{k=l..3} map_k[b,ci, h>>(k-l), w>>(k-l)]
struct PackOutParams {
    const float* map[4];
    __half* Ph[4];
    __half* Pl[4];
    int H[4];
    int npb[4];
    int blkBase[5];
};
__global__ void k_pack_out_all(const __grid_constant__ PackOutParams P){
    __shared__ float t[32][33];
    const int bid = blockIdx.x;
    int l = 0;
    if (bid >= P.blkBase[1]) l = 1;
    if (bid >= P.blkBase[2]) l = 2;
    if (bid >= P.blkBase[3]) l = 3;
    const int rel = bid - P.blkBase[l];
    const int npb = P.npb[l];
    const int bxp = rel % npb;
    const int c0  = (rel / npb) * 32;
    const int H = P.H[l], W = H;
    const int Hp = H + 2, Wp = W + 2, Np = 2 * Hp * Wp;
    const int p0 = bxp * 32;

    int px = p0 + threadIdx.x;
    int b = 0, hh = 0, ww = 0; bool inter = false;
    if (px < Np){
        b = px / (Hp * Wp); int r = px % (Hp * Wp); int hp = r / Wp, wp = r % Wp;
        if (hp >= 1 && hp <= H && wp >= 1 && wp <= W){ inter = true; hh = hp - 1; ww = wp - 1; }
    }
    #pragma unroll
    for (int dyy = 0; dyy < 32; dyy += 8){
        int ci = c0 + (int)threadIdx.y + dyy;
        float v = 0.f;
        if (inter){
            for (int k = l; k < 4; k++){
                int Wk = P.H[k];
                int sh = k - l;
                v += P.map[k][((size_t)(b * 256 + ci) * Wk + (hh >> sh)) * Wk + (ww >> sh)];
            }
        }
        t[threadIdx.y + dyy][threadIdx.x] = v;
    }
    __syncthreads();
    int ft = threadIdx.y * 32 + threadIdx.x;
    int pl = ft >> 3, sub = ft & 7;
    int px2 = p0 + pl;
    if (px2 < Np){
        size_t chStride = (size_t)2 * Hp * Wp * 32;
        int gsw = (sub >> 1) ^ ((px2 >> 1) & 3);
        size_t base = (size_t)(c0 >> 5) * chStride + (size_t)px2 * 32 + (gsw << 3) + (sub & 1) * 4;
        float v0 = t[sub*4+0][pl], v1 = t[sub*4+1][pl], v2 = t[sub*4+2][pl], v3 = t[sub*4+3][pl];
        __half h0 = __float2half_rn(v0), h1 = __float2half_rn(v1);
        __half h2 = __float2half_rn(v2), h3 = __float2half_rn(v3);
        uint32_t uh0 = (uint32_t)__half_as_ushort(h0) | ((uint32_t)__half_as_ushort(h1) << 16);
        uint32_t uh1 = (uint32_t)__half_as_ushort(h2) | ((uint32_t)__half_as_ushort(h3) << 16);
        uint2 wh; wh.x = uh0; wh.y = uh1;
        *reinterpret_cast<uint2*>(P.Ph[l] + base) = wh;
        __half l0 = __float2half_rn(v0 - __half2float(h0));
        __half l1 = __float2half_rn(v1 - __half2float(h1));
        __half l2 = __float2half_rn(v2 - __half2float(h2));
        __half l3 = __float2half_rn(v3 - __half2float(h3));
        uint32_t ul0 = (uint32_t)__half_as_ushort(l0) | ((uint32_t)__half_as_ushort(l1) << 16);
        uint32_t ul1 = (uint32_t)__half_as_ushort(l2) | ((uint32_t)__half_as_ushort(l3) << 16);
        uint2 wl; wl.x = ul0; wl.y = ul1;
        *reinterpret_cast<uint2*>(P.Pl[l] + base) = wl;
    }
}

// ================= merged multi-level fp16 2-pass implicit-conv GEMM =================
struct GemmParams {
    const __half* A;
    const __half* BhB;
    const __half* BlB;
    float*        out[4];
    const float*  bias[4];
    long aOff[4];
    long bOff[4];
    int  H[4];
    int  lgW[4];
    int  zc[4];
    int  tpz[4];
    int  blkBase[5];
    int  CH;
};

__global__ __launch_bounds__(256)
void k_gemm(const __grid_constant__ GemmParams P)
{
    extern __shared__ char dsm[];
    __shared__ __align__(8) unsigned long long mb[6];

    const int bid = blockIdx.x;
    int l = 0;
    if (bid >= P.blkBase[1]) l = 1;
    if (bid >= P.blkBase[2]) l = 2;
    if (bid >= P.blkBase[3]) l = 3;
    const int rel = bid - P.blkBase[l];
    const int zc = P.zc[l], tapsPerZ = P.tpz[l];
    const int zi = rel % zc;
    const int tt = rel / zc;
    const int m0 = (tt & 1) * 128;
    const int nt = tt >> 1;
    const int H = P.H[l], W = H, lgW = P.lgW[l];
    const __half* A  = P.A   + P.aOff[l];
    const __half* Bh = P.BhB + P.bOff[l];
    const __half* Bl = P.BlB + P.bOff[l];
    float* out = P.out[l];
    const float* bias = P.bias[l];
    const int useAtomic = (zc > 1);
    const int tapBeg = zi * tapsPerZ;
    const int CH = P.CH;

    const uint32_t smemBase = smem_u32(dsm);
    uint32_t A_OFF[4], B_OFF[2];
    #pragma unroll
    for (int s = 0; s < 4; s++) A_OFF[s] = smemBase + s * 8192u;
    B_OFF[0] = smemBase + 32768u;
    B_OFF[1] = smemBase + 32768u + 66560u;
    const uint32_t MBA = smem_u32(&mb[0]);
    const uint32_t MBB = smem_u32(&mb[4]);

    const int tid = threadIdx.x, wid = tid >> 5, lane = tid & 31;
    const int R = 256 >> lgW;
    const int Hp = H + 2, Wp = W + 2;
    const int tilesPerB = H / R;
    const int b  = nt / tilesPerB;
    const int h0 = (nt % tilesPerB) * R;
    const int q0 = (b * Hp + h0) * Wp;
    const uint32_t Bbytes = (uint32_t)(R + 2) * Wp * 64u;
    const size_t chStride = (size_t)2 * Hp * Wp * 32;

    if (tid == 0){
        #pragma unroll
        for (int i = 0; i < 6; i++) mbar_init(MBA + i * 8, 1);
    }
    __syncthreads();

    const int nA = CH * tapsPerZ;

    auto issueA = [&](int ia){
        int c = ia / tapsPerZ, tap = ia % tapsPerZ;
        const __half* src = A + ((((size_t)c * 9 + (tapBeg + tap)) * 256 + m0) << 5);
        int s = ia & 3;
        mbar_expect(MBA + s * 8, 8192u);
        bulk_cp(A_OFF[s], src, 8192u, MBA + s * 8);
    };
    auto issueB = [&](int c){
        int s = c & 1;
        mbar_expect(MBB + s * 8, 2u * Bbytes);
        bulk_cp(B_OFF[s],          Bh + (size_t)c * chStride + ((size_t)q0 << 5), Bbytes, MBB + s * 8);
        bulk_cp(B_OFF[s] + 33280u, Bl + (size_t)c * chStride + ((size_t)q0 << 5), Bbytes, MBB + s * 8);
    };

    const int lr  = lane & 7;
    const int lm8 = ((lane >> 3) & 1) * 8;
    const int lk  = lane >> 4;
    const int wm  = wid & 1;
    const int wn  = wid >> 1;
    const int rowA = wm * 64 + lm8 + lr;
    const int xorA = (lr >> 1) & 3;
    int rB[4], wB[4];
    #pragma unroll
    for (int g = 0; g < 4; g++){
        int n = wn * 64 + g * 16 + lm8 + lr;
        rB[g] = n >> lgW;
        wB[g] = n & (W - 1);
    }

    float acc[4][8][4];
    #pragma unroll
    for (int i = 0; i < 4; i++)
        #pragma unroll
        for (int j = 0; j < 8; j++)
            #pragma unroll
            for (int k = 0; k < 4; k++) acc[i][j][k] = 0.f;

    if (tid == 0){
        issueB(0);
        issueA(0);
        if (nA > 1) issueA(1);
        if (nA > 2) issueA(2);
    }

    for (int it = 0; it < nA; ++it){
        int c = it / tapsPerZ, tap = it % tapsPerZ;
        if (tid == 0){
            if (it + 3 < nA) issueA(it + 3);
            if (tap == 0 && c + 1 < CH) issueB(c + 1);
        }
        mbar_wait(MBA + (it & 3) * 8, (it >> 2) & 1);
        if (tap == 0) mbar_wait(MBB + (c & 1) * 8, (c >> 1) & 1);

        const uint32_t Ab = A_OFF[it & 3];
        const uint32_t Bb = B_OFF[c & 1];
        const int tIdx = tapBeg + tap;
        const int dy = tIdx / 3, dx = tIdx - dy * 3;

        uint32_t sAdr[4]; int xorB[4];
        #pragma unroll
        for (int g = 0; g < 4; g++){
            int s = (rB[g] + dy) * Wp + wB[g] + dx;
            sAdr[g] = Bb + (uint32_t)s * 64u;
            xorB[g] = ((q0 + s) >> 1) & 3;
        }

        #pragma unroll
        for (int ks = 0; ks < 2; ks++){
            const int gA = (2 * ks + lk) ^ xorA;
            uint32_t a[4][4];
            #pragma unroll
            for (int ma = 0; ma < 4; ma++)
                ldmx4(a[ma], Ab + (uint32_t)(rowA + ma * 16) * 64u + ((uint32_t)gA << 4));
            #pragma unroll
            for (int pass = 0; pass < 2; pass++){
                uint32_t bb[4][4];
                #pragma unroll
                for (int g = 0; g < 4; g++){
                    int gB = (2 * ks + lk) ^ xorB[g];
                    ldmx4(bb[g], sAdr[g] + (uint32_t)pass * 33280u + ((uint32_t)gB << 4));
                }
                #pragma unroll
                for (int ma = 0; ma < 4; ma++)
                    #pragma unroll
                    for (int na = 0; na < 8; na++)
                        mma16816(acc[ma][na], a[ma], bb[na >> 1][na & 1], bb[na >> 1][2 + (na & 1)]);
            }
        }
        __syncthreads();
    }

    #pragma unroll
    for (int ma = 0; ma < 4; ma++){
        int co0 = m0 + wm * 64 + ma * 16 + (lane >> 2);
        int co1 = co0 + 8;
        float bv0 = useAtomic ? 0.f : bias[co0];
        float bv1 = useAtomic ? 0.f : bias[co1];
        #pragma unroll
        for (int na = 0; na < 8; na++){
            int n = wn * 64 + na * 8 + (lane & 3) * 2;
            int r = h0 + (n >> lgW);
            int w = n & (W - 1);
            size_t i0 = ((size_t)(b * 256 + co0) * H + r) * W + w;
            size_t i1 = ((size_t)(b * 256 + co1) * H + r) * W + w;
            if (useAtomic){
                atomicAdd(&out[i0],     acc[ma][na][0]);
                atomicAdd(&out[i0 + 1], acc[ma][na][1]);
                atomicAdd(&out[i1],     acc[ma][na][2]);
                atomicAdd(&out[i1 + 1], acc[ma][na][3]);
            } else {
                float2 v0; v0.x = acc[ma][na][0] + bv0; v0.y = acc[ma][na][1] + bv0;
                float2 v1; v1.x = acc[ma][na][2] + bv1; v1.y = acc[ma][na][3] + bv1;
                *reinterpret_cast<float2*>(&out[i0]) = v0;
                *reinterpret_cast<float2*>(&out[i1]) = v1;
            }
        }
    }
}

// ---------------- host orchestration (8 launches total) ----------------
extern "C" void kernel_launch(void* const* d_in, const int* in_sizes, int n_in,
                              void* d_out, int out_size)
{
    const float *x[4]={0,0,0,0}, *rx[4]={0,0,0,0};
    const float *wm[4]={0,0,0,0}, *bm[4]={0,0,0,0}, *wo[4]={0,0,0,0}, *bo[4]={0,0,0,0};
    int wmi = 0, woi = 0, bi = 0;
    for (int i = 0; i < n_in; i++){
        int s = in_sizes[i];
        int lvl = -1;
        if      (s == 2*256*128*128) lvl = 0;
        else if (s == 2*256*64*64)   lvl = 1;
        else if (s == 2*256*32*32)   lvl = 2;
        else if (s == 2*256*16*16)   lvl = 3;
        if (lvl >= 0){
            if (!x[lvl]) x[lvl] = (const float*)d_in[i];
            else         rx[lvl] = (const float*)d_in[i];
        }
        else if (s == 1845504) wm[wmi++] = (const float*)d_in[i];
        else if (s ==  589824) wo[woi++] = (const float*)d_in[i];
        else if (s ==     256){
            if ((bi & 1) == 0) bm[bi >> 1] = (const float*)d_in[i];
            else               bo[bi >> 1] = (const float*)d_in[i];
            bi++;
        }
    }

    float *corrB, *mapB;
    __half *wmh, *woh, *amh, *aml, *aoh, *aol;
    cudaGetSymbolAddress((void**)&corrB, g_corr);
    cudaGetSymbolAddress((void**)&mapB,  g_map);
    cudaGetSymbolAddress((void**)&wmh, g_wm_h);
    cudaGetSymbolAddress((void**)&woh, g_wo_h);
    cudaGetSymbolAddress((void**)&amh, g_am_h); cudaGetSymbolAddress((void**)&aml, g_am_l);
    cudaGetSymbolAddress((void**)&aoh, g_ao_h); cudaGetSymbolAddress((void**)&aol, g_ao_l);

    cudaFuncSetAttribute(k_gemm, cudaFuncAttributeMaxDynamicSharedMemorySize, 165888);

    const int  Hl[4]      = {128, 64, 32, 16};
    const int  lgWl[4]    = {7, 6, 5, 4};
    const int  HWl[4]     = {16384, 4096, 1024, 256};
    const long corrOff[4] = {0, 9469952, 11837440, 12429312};
    const long mapOff[4]  = {0, 8388608, 10485760, 11010048};
    const long amOff[4]   = {0, 28121600, 35369984, 37293568};
    const long aoOff[4]   = {0, 8652800, 10883072, 11474944};
    const long wmOff[4]   = {0, 1916928, 3833856, 5750784};
    const long woOff[4]   = {0, 589824, 1179648, 1769472};
    const int  zl[4]      = {1, 3, 9, 9};
    const int  tpzl[4]    = {9, 3, 1, 1};
    float* outp = (float*)d_out;

    int gemmBase[5]; gemmBase[0] = 0;
    for (int l = 0; l < 4; l++)
        gemmBase[l + 1] = gemmBase[l] + (2 * HWl[l] / 256) * 2 * zl[l];  // {0,256,448,592,628}

    // ---- launch 0: init map buffers (levels 1-3, atomic) ----
    {
        InitParams P;
        long tot = 0;
        for (int r = 0; r < 3; r++){
            int l = r + 1;
            P.out[r] = mapB + mapOff[l]; P.bias[r] = bm[l]; P.HW[r] = HWl[l];
            P.base[r] = tot; tot += 2L * 256 * HWl[l];
        }
        P.base[3] = tot;
        k_init_all<<<(int)((tot + 255) / 256), 256>>>(P);
    }
    // ---- launch 1: init out buffers (levels 1-3, atomic) ----
    {
        InitParams P;
        long tot = 0;
        for (int r = 0; r < 3; r++){
            int l = r + 1;
            P.out[r] = outp + mapOff[l]; P.bias[r] = bo[l]; P.HW[r] = HWl[l];
            P.base[r] = tot; tot += 2L * 256 * HWl[l];
        }
        P.base[3] = tot;
        k_init_all<<<(int)((tot + 255) / 256), 256>>>(P);
    }
    // ---- launch 2: pack all weights ----
    {
        PackWParams P;
        long tot = 0;
        for (int l = 0; l < 4; l++){
            P.src[l] = wm[l]; P.dst[l] = wmh + wmOff[l]; P.Cin[l] = 801; P.Cpad[l] = 832;
            P.base[l] = tot; tot += 256L * 832;
        }
        for (int l = 0; l < 4; l++){
            P.src[4+l] = wo[l]; P.dst[4+l] = woh + woOff[l]; P.Cin[4+l] = 256; P.Cpad[4+l] = 256;
            P.base[4+l] = tot; tot += 256L * 256;
        }
        P.base[8] = tot;
        k_pack_w_all<<<(int)((tot + 255) / 256), 256>>>(P);
    }
    // ---- launch 3: all correlation volumes ----
    {
        CorrParams P;
        int base = 0;
        for (int l = 0; l < 4; l++){
            P.x[l] = x[l]; P.rx[l] = rx[l]; P.out[l] = corrB + corrOff[l];
            P.H[l] = Hl[l];
            P.grp[l] = (Hl[l] >= 32) ? 8 : 4;
            P.GX[l] = Hl[l] / (P.grp[l] * 4);
            P.blkBase[l] = base;
            base += P.GX[l] * Hl[l] * 2;
        }
        P.blkBase[4] = base;
        k_corr_all<<<base, 136>>>(P);
    }
    // ---- launch 4: pack map activations ----
    int npbl[4];
    for (int l = 0; l < 4; l++){
        int Np = 2 * (Hl[l] + 2) * (Hl[l] + 2);
        npbl[l] = (Np + 31) / 32;
    }
    {
        PackMapParams P;
        int base = 0;
        for (int l = 0; l < 4; l++){
            P.x[l] = x[l]; P.rx[l] = rx[l]; P.corr[l] = corrB + corrOff[l];
            P.Ph[l] = amh + amOff[l]; P.Pl[l] = aml + amOff[l];
            P.H[l] = Hl[l]; P.npb[l] = npbl[l];
            P.blkBase[l] = base;
            base += npbl[l] * 26;
        }
        P.blkBase[4] = base;
        k_pack_map_all<<<base, dim3(32, 8)>>>(P);
    }
    // ---- launch 5: merged map GEMM (profiled by ncu -s 5) ----
    {
        GemmParams P;
        P.A = wmh; P.BhB = amh; P.BlB = aml;
        for (int l = 0; l < 4; l++){
            P.out[l] = mapB + mapOff[l]; P.bias[l] = bm[l];
            P.aOff[l] = wmOff[l]; P.bOff[l] = amOff[l];
            P.H[l] = Hl[l]; P.lgW[l] = lgWl[l]; P.zc[l] = zl[l]; P.tpz[l] = tpzl[l];
        }
        for (int i = 0; i < 5; i++) P.blkBase[i] = gemmBase[i];
        P.CH = 26;
        k_gemm<<<gemmBase[4], 256, 165888>>>(P);
    }
    // ---- launch 6: pack out activations with fused upsample cascade ----
    {
        PackOutParams P;
        int base = 0;
        for (int l = 0; l < 4; l++){
            P.map[l] = mapB + mapOff[l];
            P.Ph[l] = aoh + aoOff[l]; P.Pl[l] = aol + aoOff[l];
            P.H[l] = Hl[l]; P.npb[l] = npbl[l];
            P.blkBase[l] = base;
            base += npbl[l] * 8;
        }
        P.blkBase[4] = base;
        k_pack_out_all<<<base, dim3(32, 8)>>>(P);
    }
    // ---- launch 7: merged out GEMM -> d_out ----
    {
        GemmParams P;
        P.A = woh; P.BhB = aoh; P.BlB = aol;
        for (int l = 0; l < 4; l++){
            P.out[l] = outp + mapOff[l]; P.bias[l] = bo[l];
            P.aOff[l] = woOff[l]; P.bOff[l] = aoOff[l];
            P.H[l] = Hl[l]; P.lgW[l] = lgWl[l]; P.zc[l] = zl[l]; P.tpz[l] = tpzl[l];
        }
        for (int i = 0; i < 5; i++) P.blkBase[i] = gemmBase[i];
        P.CH = 8;
        k_gemm<<<gemmBase[4], 256, 165888>>>(P);
    }
}